// round 11
// baseline (speedup 1.0000x reference)
#include <cuda_runtime.h>
#include <cuda_fp16.h>
#include <math.h>
#include <stdint.h>

#define BATCH 2
#define SEQ   2048
#define DIM   1024
#define NH    16
#define HD    64
#define BT    (BATCH*SEQ)      // 4096
#define QKVN  (3*DIM)          // 3072

// Scratch (static device arrays; no allocations allowed)
__device__ __half g_q[BATCH*NH*SEQ*HD];     // [B,H,T,D]
__device__ __half g_k[BATCH*NH*SEQ*HD];     // [B,H,T,D]
__device__ __half g_vt[BATCH*NH*HD*SEQ];    // [B,H,D,T]  (transposed V)
__device__ __half g_attn[BT*DIM];           // [B*T, C]
__device__ __half g_xh[BT*DIM];             // fp16(x)
__device__ __half g_wqkvh[QKVN*DIM];        // fp16(W_qkv^T)  [N][K]
__device__ __half g_wprojh[DIM*DIM];        // fp16(W_proj^T) [N][K]

// ---------------------------------------------------------------------------
__device__ __forceinline__ uint32_t smem_u32(const void* p) {
    uint32_t a;
    asm("{ .reg .u64 t; cvta.to.shared.u64 t, %1; cvt.u32.u64 %0, t; }" : "=r"(a) : "l"(p));
    return a;
}
__device__ __forceinline__ uint32_t pack_h2(float lo, float hi) {
    __half2 h = __floats2half2_rn(lo, hi);
    return *reinterpret_cast<uint32_t*>(&h);
}
#define CP16(dst, src) \
    asm volatile("cp.async.cg.shared.global [%0], [%1], 16;" :: "r"(dst), "l"(src) : "memory")
#define CPCOMMIT() asm volatile("cp.async.commit_group;" ::: "memory")
#define CPWAIT(n)  asm volatile("cp.async.wait_group %0;" :: "n"(n) : "memory")

// m16n8k16 fp16 mma, fp32 accum
__device__ __forceinline__ void mma16(float* c, const uint32_t* a, uint32_t b0, uint32_t b1) {
    asm volatile(
        "mma.sync.aligned.m16n8k16.row.col.f32.f16.f16.f32 "
        "{%0,%1,%2,%3},{%4,%5,%6,%7},{%8,%9},{%0,%1,%2,%3};\n"
        : "+f"(c[0]), "+f"(c[1]), "+f"(c[2]), "+f"(c[3])
        : "r"(a[0]), "r"(a[1]), "r"(a[2]), "r"(a[3]), "r"(b0), "r"(b1));
}

// ldmatrix x4: four 8x8 b16 matrices; lane l supplies row address
__device__ __forceinline__ void ldsm4(uint32_t* r, uint32_t addr) {
    asm volatile("ldmatrix.sync.aligned.m8n8.x4.shared.b16 {%0,%1,%2,%3}, [%4];"
                 : "=r"(r[0]), "=r"(r[1]), "=r"(r[2]), "=r"(r[3]) : "r"(addr));
}

// ---------------------------------------------------------------------------
// pre-convert kernels
// ---------------------------------------------------------------------------
__global__ void cvt_h_kernel(const float* __restrict__ src, __half* __restrict__ dst, int n) {
    int i = (blockIdx.x * 256 + threadIdx.x) * 8;
    if (i < n) {
        float4 v0 = *(const float4*)(src + i);
        float4 v1 = *(const float4*)(src + i + 4);
        uint4 u = { pack_h2(v0.x, v0.y), pack_h2(v0.z, v0.w),
                    pack_h2(v1.x, v1.y), pack_h2(v1.z, v1.w) };
        *(uint4*)(dst + i) = u;
    }
}

// src [K][N] fp32 row-major -> dst [N][K] fp16
__global__ void cvt_tr_kernel(const float* __restrict__ src, __half* __restrict__ dst,
                              int K, int N) {
    __shared__ float tile[32][33];
    const int n0 = blockIdx.x * 32, k0 = blockIdx.y * 32;
    const int tx = threadIdx.x, ty = threadIdx.y;
    for (int i = ty; i < 32; i += 8)
        tile[i][tx] = src[(size_t)(k0 + i) * N + n0 + tx];
    __syncthreads();
    for (int i = ty; i < 32; i += 8)
        dst[(size_t)(n0 + i) * K + k0 + tx] = __float2half_rn(tile[tx][i]);
}

// ---------------------------------------------------------------------------
// fp16 GEMM: tile 128(M) x 64(N), BK=64, 2 stages cp.async, 256 threads,
// 3 CTAs/SM (24 warps/SM), warp tile 32x32, ldmatrix at 144 B stride.
// A [M,1024] fp16 row-major; B pre-transposed [N][1024] (k-contiguous).
// Smem per stage: A [128][72] halfs (18432 B) + B [64][72] (9216 B);
// 2 stages = 55296 B -> 3 CTAs/SM. Per-element k-order identical to r10.
// MODE 0: QKV scatter (q,k normal; v transposed) ; MODE 1: C = acc + bias.
// ---------------------------------------------------------------------------
#define GA_ST 18432
#define GB_ST 9216
#define GSTAGE (GA_ST + GB_ST)         // 27648
#define GSMEM (2 * GSTAGE)             // 55296 B -> 3 CTAs/SM

__device__ __forceinline__ void g_issue64(const __half* A, const __half* Bt,
                                          int m0, int n0, int t, int tid, uint32_t sb) {
    const uint32_t abase = sb + (t & 1) * GSTAGE;
    const uint32_t bbase = abase + GA_ST;
#pragma unroll
    for (int i = 0; i < 4; i++) {
        const int id = tid + i * 256;
        const int r = id >> 3, c = id & 7;
        CP16(abase + r * 144 + c * 16, A + (size_t)(m0 + r) * 1024 + t * 64 + c * 8);
    }
#pragma unroll
    for (int i = 0; i < 2; i++) {
        const int id = tid + i * 256;
        const int r = id >> 3, c = id & 7;
        CP16(bbase + r * 144 + c * 16, Bt + (size_t)(n0 + r) * 1024 + t * 64 + c * 8);
    }
    CPCOMMIT();
}

template<int MODE>
__global__ __launch_bounds__(256, 3)
void gemm_h(const __half* __restrict__ A, const __half* __restrict__ Bt,
            const float* __restrict__ bias, float* __restrict__ C, int N,
            __half* __restrict__ oq, __half* __restrict__ ok, __half* __restrict__ ovt)
{
    extern __shared__ uint32_t sw[];
    const uint32_t sb = smem_u32(sw);

    const int tid  = threadIdx.x;
    const int lane = tid & 31;
    const int wid  = tid >> 5;
    const int g    = lane >> 2;
    const int tg   = lane & 3;
    const int warp_m = (wid & 3) * 32;     // 4 warp rows
    const int warp_n = (wid >> 2) * 32;    // 2 warp cols
    const int m0 = blockIdx.y * 128;
    const int n0 = blockIdx.x * 64;

    // ldmatrix per-lane addressing (144 B stride)
    const int lrow = (lane & 7) + ((lane >> 3) & 1) * 8;
    const int lcol = lane >> 4;                       // 0/1
    const uint32_t aOff = (uint32_t)((warp_m + lrow) * 144 + lcol * 16);
    const uint32_t bOff = (uint32_t)((warp_n + lrow) * 144 + lcol * 16);

    float acc[2][4][4];
#pragma unroll
    for (int mt = 0; mt < 2; mt++)
#pragma unroll
        for (int nt = 0; nt < 4; nt++)
#pragma unroll
            for (int i = 0; i < 4; i++) acc[mt][nt][i] = 0.f;

    g_issue64(A, Bt, m0, n0, 0, tid, sb);

    for (int t = 0; t < 16; ++t) {
        CPWAIT(0);
        __syncthreads();
        if (t + 1 < 16) g_issue64(A, Bt, m0, n0, t + 1, tid, sb);

        const uint32_t aS = sb + (t & 1) * GSTAGE;
        const uint32_t bS = aS + GA_ST;

#pragma unroll
        for (int kt = 0; kt < 4; ++kt) {
            uint32_t afr[2][4];
            ldsm4(afr[0], aS + aOff + kt * 32);
            ldsm4(afr[1], aS + aOff + 2304 + kt * 32);       // +16 rows
            uint32_t bfr[2][4];
#pragma unroll
            for (int ntp = 0; ntp < 2; ntp++)
                ldsm4(bfr[ntp], bS + bOff + ntp * 2304 + kt * 32);
#pragma unroll
            for (int mt = 0; mt < 2; mt++)
#pragma unroll
                for (int ntp = 0; ntp < 2; ntp++) {
                    mma16(acc[mt][2*ntp],   afr[mt], bfr[ntp][0], bfr[ntp][2]);
                    mma16(acc[mt][2*ntp+1], afr[mt], bfr[ntp][1], bfr[ntp][3]);
                }
        }
    }

    // epilogue
    const int rowB = m0 + warp_m;
    const int colB = n0 + warp_n;
#pragma unroll
    for (int mt = 0; mt < 2; mt++) {
#pragma unroll
        for (int nt = 0; nt < 4; nt++) {
            const int r = rowB + mt * 16 + g;
            const int c = colB + nt * 8 + 2 * tg;
            const float bv0 = bias[c], bv1 = bias[c + 1];
            const float v00 = acc[mt][nt][0] + bv0;
            const float v01 = acc[mt][nt][1] + bv1;
            const float v10 = acc[mt][nt][2] + bv0;
            const float v11 = acc[mt][nt][3] + bv1;
            if (MODE == 0) {
                const int sel = c >> 10;
                const int cc  = c & 1023;
                const int h   = cc >> 6;
                const int d   = cc & 63;
                const int b0_ = r >> 11,        t0_ = r & 2047;
                const int b1_ = (r + 8) >> 11,  t1_ = (r + 8) & 2047;
                if (sel < 2) {
                    __half* dst = (sel == 0) ? oq : ok;
                    const size_t i0 = (((size_t)(b0_ * NH + h) * SEQ) + t0_) * HD + d;
                    const size_t i1 = (((size_t)(b1_ * NH + h) * SEQ) + t1_) * HD + d;
                    *(uint32_t*)&dst[i0] = pack_h2(v00, v01);
                    *(uint32_t*)&dst[i1] = pack_h2(v10, v11);
                } else {
                    // V transposed: [B,H,D,T]
                    const size_t base0 = ((size_t)(b0_ * NH + h) * HD + d) * SEQ + t0_;
                    const size_t base1 = ((size_t)(b1_ * NH + h) * HD + d) * SEQ + t1_;
                    ovt[base0]       = __float2half_rn(v00);
                    ovt[base0 + SEQ] = __float2half_rn(v01);
                    ovt[base1]       = __float2half_rn(v10);
                    ovt[base1 + SEQ] = __float2half_rn(v11);
                }
            } else {
                *(float2*)&C[(size_t)r * N + c]       = make_float2(v00, v01);
                *(float2*)&C[(size_t)(r + 8) * N + c] = make_float2(v10, v11);
            }
        }
    }
}

// ---------------------------------------------------------------------------
// Flash attention, fp16 m16n8k16, Br=128 x Bc=64, 256 threads (8 warps x 16
// rows), 2 CTAs/SM. FA2-style: P stays in registers; Q pre-scaled by 0.125.
// K [t][d], V transposed [d][t]; smem stride 144 B (LDSM conflict-free).
// (unchanged from round 10 — passing, near its MUFU-bound ceiling)
// ---------------------------------------------------------------------------
#define AST 4608                       // words per region: 128*36 (Q) = 2*64*36 (K/V)
#define ASMEM (3 * AST * 4)            // 55296 B -> 2 CTAs/SM

__device__ __forceinline__ void issue_kv(const __half* k, const __half* vt,
                                         int bh, int kb, int buf, int tid,
                                         uint32_t kbase, uint32_t vbase) {
    const __half* ksrc = k  + ((size_t)bh * SEQ + (size_t)kb * 64) * HD;
    const __half* vsrc = vt + (size_t)bh * HD * SEQ + (size_t)kb * 64;
    const uint32_t kb_ = kbase + buf * (64 * 144);
    const uint32_t vb_ = vbase + buf * (64 * 144);
#pragma unroll
    for (int i = 0; i < 2; i++) {
        const int id = tid + i * 256;
        const int r = id >> 3, c = id & 7;
        CP16(kb_ + r * 144 + c * 16, ksrc + (size_t)r * HD + c * 8);
        CP16(vb_ + r * 144 + c * 16, vsrc + (size_t)r * SEQ + c * 8);
    }
    CPCOMMIT();
}

__global__ __launch_bounds__(256, 2)
void attn_h(const __half* __restrict__ q, const __half* __restrict__ k,
            const __half* __restrict__ vt, __half* __restrict__ out)
{
    extern __shared__ uint32_t sw[];
    const uint32_t sb    = smem_u32(sw);
    const uint32_t kbase = sb + AST * 4;
    const uint32_t vbase = sb + 2 * AST * 4;

    const int tid  = threadIdx.x;
    const int lane = tid & 31;
    const int wid  = tid >> 5;
    const int g    = lane >> 2;
    const int tg   = lane & 3;
    const int wbase = wid * 16;

    // ldmatrix per-lane addressing
    const int lrow = (lane & 7) + ((lane >> 3) & 1) * 8;
    const int lcol = lane >> 4;
    const uint32_t qpOff = (uint32_t)((wbase + lrow) * 144 + lcol * 16);
    const uint32_t kvOff = (uint32_t)(lrow * 144 + lcol * 16);

    const int bh = blockIdx.y;
    const int qb = (gridDim.x - 1) - blockIdx.x;   // big tiles first
    const int b_ = bh >> 4;
    const int h  = bh & 15;
    const int nkv = 2 * qb + 2;

    // prologue: G0 = Q + KV0, G1 = KV1
    {
        const __half* qsrc = q + ((size_t)bh * SEQ + (size_t)qb * 128) * HD;
#pragma unroll
        for (int i = 0; i < 4; i++) {
            const int id = tid + i * 256;
            const int r = id >> 3, c = id & 7;
            CP16(sb + r * 144 + c * 16, qsrc + (size_t)r * HD + c * 8);
        }
        const __half* ksrc = k  + (size_t)bh * SEQ * HD;
        const __half* vsrc = vt + (size_t)bh * HD * SEQ;
#pragma unroll
        for (int i = 0; i < 2; i++) {
            const int id = tid + i * 256;
            const int r = id >> 3, c = id & 7;
            CP16(kbase + r * 144 + c * 16, ksrc + (size_t)r * HD + c * 8);
            CP16(vbase + r * 144 + c * 16, vsrc + (size_t)r * SEQ + c * 8);
        }
        CPCOMMIT();
        issue_kv(k, vt, bh, 1, 1, tid, kbase, vbase);
    }
    CPWAIT(1);
    __syncthreads();

    // Q fragments in registers, pre-scaled by 1/sqrt(64)=0.125 (exact in fp16)
    uint32_t qf[4][4];
    {
        const __half2 sc = __half2half2(__float2half_rn(0.125f));
#pragma unroll
        for (int kt = 0; kt < 4; kt++) {
            ldsm4(qf[kt], sb + qpOff + kt * 32);
#pragma unroll
            for (int i = 0; i < 4; i++) {
                __half2 v = *reinterpret_cast<__half2*>(&qf[kt][i]);
                v = __hmul2(v, sc);
                qf[kt][i] = *reinterpret_cast<uint32_t*>(&v);
            }
        }
    }

    float m0 = -INFINITY, m1 = -INFINITY, l0 = 0.f, l1 = 0.f;
    float O[8][4];
#pragma unroll
    for (int nt = 0; nt < 8; nt++)
#pragma unroll
        for (int i = 0; i < 4; i++) O[nt][i] = 0.f;

    for (int kb = 0; kb < nkv; ++kb) {
        if (kb > 0) {
            if (kb + 1 < nkv) { CPWAIT(1); } else { CPWAIT(0); }
            __syncthreads();
        }
        const uint32_t kB = kbase + (kb & 1) * (64 * 144);
        const uint32_t vB = vbase + (kb & 1) * (64 * 144);

        // S = (Q/8) @ K^T
        float s_[8][4];
#pragma unroll
        for (int nt = 0; nt < 8; nt++)
#pragma unroll
            for (int i = 0; i < 4; i++) s_[nt][i] = 0.f;
#pragma unroll
        for (int kt = 0; kt < 4; kt++) {
            uint32_t bfr[4][4];
#pragma unroll
            for (int ntp = 0; ntp < 4; ntp++)
                ldsm4(bfr[ntp], kB + kvOff + ntp * 2304 + kt * 32);  // 16*144
#pragma unroll
            for (int ntp = 0; ntp < 4; ntp++) {
                mma16(s_[2*ntp],   qf[kt], bfr[ntp][0], bfr[ntp][2]);
                mma16(s_[2*ntp+1], qf[kt], bfr[ntp][1], bfr[ntp][3]);
            }
        }

        // causal mask (only in the last two kv tiles)
        if (kb >= 2 * qb) {
            const int rg0 = qb * 128 + wbase + g;
#pragma unroll
            for (int nt = 0; nt < 8; nt++) {
                const int cg = kb * 64 + nt * 8 + 2 * tg;
                if (cg > rg0)         s_[nt][0] = -INFINITY;
                if (cg + 1 > rg0)     s_[nt][1] = -INFINITY;
                if (cg > rg0 + 8)     s_[nt][2] = -INFINITY;
                if (cg + 1 > rg0 + 8) s_[nt][3] = -INFINITY;
            }
        }

        // online softmax
        float mx0 = -INFINITY, mx1 = -INFINITY;
#pragma unroll
        for (int nt = 0; nt < 8; nt++) {
            mx0 = fmaxf(mx0, fmaxf(s_[nt][0], s_[nt][1]));
            mx1 = fmaxf(mx1, fmaxf(s_[nt][2], s_[nt][3]));
        }
#pragma unroll
        for (int off = 1; off < 4; off <<= 1) {
            mx0 = fmaxf(mx0, __shfl_xor_sync(0xffffffffu, mx0, off));
            mx1 = fmaxf(mx1, __shfl_xor_sync(0xffffffffu, mx1, off));
        }
        const float mn0 = fmaxf(m0, mx0);
        const float mn1 = fmaxf(m1, mx1);
        const float al0 = __expf(m0 - mn0);
        const float al1 = __expf(m1 - mn1);
        m0 = mn0; m1 = mn1;

        float rs0 = 0.f, rs1 = 0.f;
#pragma unroll
        for (int nt = 0; nt < 8; nt++) {
            s_[nt][0] = __expf(s_[nt][0] - mn0); rs0 += s_[nt][0];
            s_[nt][1] = __expf(s_[nt][1] - mn0); rs0 += s_[nt][1];
            s_[nt][2] = __expf(s_[nt][2] - mn1); rs1 += s_[nt][2];
            s_[nt][3] = __expf(s_[nt][3] - mn1); rs1 += s_[nt][3];
        }
#pragma unroll
        for (int off = 1; off < 4; off <<= 1) {
            rs0 += __shfl_xor_sync(0xffffffffu, rs0, off);
            rs1 += __shfl_xor_sync(0xffffffffu, rs1, off);
        }
        l0 = l0 * al0 + rs0;
        l1 = l1 * al1 + rs1;
#pragma unroll
        for (int nt = 0; nt < 8; nt++) {
            O[nt][0] *= al0; O[nt][1] *= al0;
            O[nt][2] *= al1; O[nt][3] *= al1;
        }

        // P stays in registers: S C-fragment == PV A-fragment (fp16 packed)
        // O += P @ V   (B = V^T [d][t], k-contiguous)
#pragma unroll
        for (int kt = 0; kt < 4; kt++) {
            uint32_t pa[4];
            pa[0] = pack_h2(s_[2*kt][0],   s_[2*kt][1]);
            pa[1] = pack_h2(s_[2*kt][2],   s_[2*kt][3]);
            pa[2] = pack_h2(s_[2*kt+1][0], s_[2*kt+1][1]);
            pa[3] = pack_h2(s_[2*kt+1][2], s_[2*kt+1][3]);
            uint32_t bfr[4][4];
#pragma unroll
            for (int ntp = 0; ntp < 4; ntp++)
                ldsm4(bfr[ntp], vB + kvOff + ntp * 2304 + kt * 32);
#pragma unroll
            for (int ntp = 0; ntp < 4; ntp++) {
                mma16(O[2*ntp],   pa, bfr[ntp][0], bfr[ntp][2]);
                mma16(O[2*ntp+1], pa, bfr[ntp][1], bfr[ntp][3]);
            }
        }
        __syncthreads();
        if (kb + 2 < nkv) issue_kv(k, vt, bh, kb + 2, kb & 1, tid, kbase, vbase);
    }

    // normalize, write fp16 to g_attn [B*T, C]
    const float inv0 = 1.f / l0;
    const float inv1 = 1.f / l1;
    const int t0 = qb * 128 + wbase + g;
#pragma unroll
    for (int nt = 0; nt < 8; nt++) {
        const int c = h * HD + nt * 8 + 2 * tg;
        *(uint32_t*)&out[((size_t)(b_ * SEQ + t0)) * DIM + c] =
            pack_h2(O[nt][0] * inv0, O[nt][1] * inv0);
        *(uint32_t*)&out[((size_t)(b_ * SEQ + t0 + 8)) * DIM + c] =
            pack_h2(O[nt][2] * inv1, O[nt][3] * inv1);
    }
}

// ---------------------------------------------------------------------------
extern "C" void kernel_launch(void* const* d_in, const int* in_sizes, int n_in,
                              void* d_out, int out_size)
{
    const float* x     = (const float*)d_in[0];
    const float* Wqkv  = (const float*)d_in[1];
    const float* bqkv  = (const float*)d_in[2];
    const float* Wproj = (const float*)d_in[3];
    const float* bproj = (const float*)d_in[4];
    float* out = (float*)d_out;

    __half *gq, *gk, *gvt, *gattn, *gxh, *gwqkvh, *gwprojh;
    cudaGetSymbolAddress((void**)&gq, g_q);
    cudaGetSymbolAddress((void**)&gk, g_k);
    cudaGetSymbolAddress((void**)&gvt, g_vt);
    cudaGetSymbolAddress((void**)&gattn, g_attn);
    cudaGetSymbolAddress((void**)&gxh, g_xh);
    cudaGetSymbolAddress((void**)&gwqkvh, g_wqkvh);
    cudaGetSymbolAddress((void**)&gwprojh, g_wprojh);

    cudaFuncSetAttribute(gemm_h<0>, cudaFuncAttributeMaxDynamicSharedMemorySize, GSMEM);
    cudaFuncSetAttribute(gemm_h<1>, cudaFuncAttributeMaxDynamicSharedMemorySize, GSMEM);
    cudaFuncSetAttribute(attn_h,   cudaFuncAttributeMaxDynamicSharedMemorySize, ASMEM);

    // 0) fp16 pre-convert (x elementwise; weights converted + transposed to [N][K])
    cvt_h_kernel<<<(BT*DIM)/2048, 256>>>(x, gxh, BT*DIM);
    cvt_tr_kernel<<<dim3(QKVN/32, DIM/32), dim3(32, 8)>>>(Wqkv, gwqkvh, DIM, QKVN);
    cvt_tr_kernel<<<dim3(DIM/32, DIM/32), dim3(32, 8)>>>(Wproj, gwprojh, DIM, DIM);

    // 1) QKV projection + head scatter (V transposed)
    {
        dim3 grid(QKVN / 64, BT / 128);    // (48, 32)
        gemm_h<0><<<grid, 256, GSMEM>>>(gxh, gwqkvh, bqkv, nullptr,
                                        QKVN, gq, gk, gvt);
    }
    // 2) Causal flash attention
    {
        dim3 grid(SEQ / 128, BATCH * NH);  // (16, 32)
        attn_h<<<grid, 256, ASMEM>>>(gq, gk, gvt, gattn);
    }
    // 3) Output projection
    {
        dim3 grid(DIM / 64, BT / 128);     // (16, 32)
        gemm_h<1><<<grid, 256, GSMEM>>>(gattn, gwprojh, bproj, out,
                                        DIM, nullptr, nullptr, nullptr);
    }
    (void)in_sizes; (void)n_in; (void)out_size;
}

// round 12
// speedup vs baseline: 1.0076x; 1.0076x over previous
#include <cuda_runtime.h>
#include <cuda_fp16.h>
#include <math.h>
#include <stdint.h>

#define BATCH 2
#define SEQ   2048
#define DIM   1024
#define NH    16
#define HD    64
#define BT    (BATCH*SEQ)      // 4096
#define QKVN  (3*DIM)          // 3072

// Scratch (static device arrays; no allocations allowed)
__device__ __half g_q[BATCH*NH*SEQ*HD];     // [B,H,T,D]
__device__ __half g_k[BATCH*NH*SEQ*HD];     // [B,H,T,D]
__device__ __half g_vt[BATCH*NH*HD*SEQ];    // [B,H,D,T]  (transposed V)
__device__ __half g_attn[BT*DIM];           // [B*T, C]
__device__ __half g_xh[BT*DIM];             // fp16(x)
__device__ __half g_wqkvh[QKVN*DIM];        // fp16(W_qkv^T)  [N][K]
__device__ __half g_wprojh[DIM*DIM];        // fp16(W_proj^T) [N][K]

// ---------------------------------------------------------------------------
__device__ __forceinline__ uint32_t smem_u32(const void* p) {
    uint32_t a;
    asm("{ .reg .u64 t; cvta.to.shared.u64 t, %1; cvt.u32.u64 %0, t; }" : "=r"(a) : "l"(p));
    return a;
}
__device__ __forceinline__ uint32_t pack_h2(float lo, float hi) {
    __half2 h = __floats2half2_rn(lo, hi);
    return *reinterpret_cast<uint32_t*>(&h);
}
#define CP16(dst, src) \
    asm volatile("cp.async.cg.shared.global [%0], [%1], 16;" :: "r"(dst), "l"(src) : "memory")
#define CPCOMMIT() asm volatile("cp.async.commit_group;" ::: "memory")
#define CPWAIT(n)  asm volatile("cp.async.wait_group %0;" :: "n"(n) : "memory")

// m16n8k16 fp16 mma, fp32 accum
__device__ __forceinline__ void mma16(float* c, const uint32_t* a, uint32_t b0, uint32_t b1) {
    asm volatile(
        "mma.sync.aligned.m16n8k16.row.col.f32.f16.f16.f32 "
        "{%0,%1,%2,%3},{%4,%5,%6,%7},{%8,%9},{%0,%1,%2,%3};\n"
        : "+f"(c[0]), "+f"(c[1]), "+f"(c[2]), "+f"(c[3])
        : "r"(a[0]), "r"(a[1]), "r"(a[2]), "r"(a[3]), "r"(b0), "r"(b1));
}

// ldmatrix x4: four 8x8 b16 matrices; lane l supplies row address
__device__ __forceinline__ void ldsm4(uint32_t* r, uint32_t addr) {
    asm volatile("ldmatrix.sync.aligned.m8n8.x4.shared.b16 {%0,%1,%2,%3}, [%4];"
                 : "=r"(r[0]), "=r"(r[1]), "=r"(r[2]), "=r"(r[3]) : "r"(addr));
}

// ---------------------------------------------------------------------------
// pre-convert kernels
// ---------------------------------------------------------------------------
__global__ void cvt_h_kernel(const float* __restrict__ src, __half* __restrict__ dst, int n) {
    int i = (blockIdx.x * 256 + threadIdx.x) * 8;
    if (i < n) {
        float4 v0 = *(const float4*)(src + i);
        float4 v1 = *(const float4*)(src + i + 4);
        uint4 u = { pack_h2(v0.x, v0.y), pack_h2(v0.z, v0.w),
                    pack_h2(v1.x, v1.y), pack_h2(v1.z, v1.w) };
        *(uint4*)(dst + i) = u;
    }
}

// src [K][N] fp32 row-major -> dst [N][K] fp16
__global__ void cvt_tr_kernel(const float* __restrict__ src, __half* __restrict__ dst,
                              int K, int N) {
    __shared__ float tile[32][33];
    const int n0 = blockIdx.x * 32, k0 = blockIdx.y * 32;
    const int tx = threadIdx.x, ty = threadIdx.y;
    for (int i = ty; i < 32; i += 8)
        tile[i][tx] = src[(size_t)(k0 + i) * N + n0 + tx];
    __syncthreads();
    for (int i = ty; i < 32; i += 8)
        dst[(size_t)(n0 + i) * K + k0 + tx] = __float2half_rn(tile[tx][i]);
}

// ---------------------------------------------------------------------------
// fp16 GEMM: tile 128x128, BK=64, 3 stages cp.async (prefetch distance 2,
// CPWAIT(1) -> one stage always in flight during compute), 256 threads,
// 2 CTAs/SM, warp tile 32x64, ldmatrix at 144 B stride.
// A [M,1024] fp16 row-major; B pre-transposed [N][1024] (k-contiguous).
// Smem per stage: A [128][72] halfs (18432 B) + B same; 3 stages = 110592 B.
// MODE 0: QKV scatter (q,k normal; v transposed) ; MODE 1: C = acc + bias.
// ---------------------------------------------------------------------------
#define GA_ST 18432
#define GSTAGE (2 * GA_ST)             // A+B per stage: 36864
#define GSMEM (3 * GSTAGE)             // 110592 B -> 2 CTAs/SM (221184 < 227KB)

__device__ __forceinline__ void g_issue64(const __half* A, const __half* Bt,
                                          int m0, int n0, int t, int tid, uint32_t sb) {
    const uint32_t abase = sb + (t % 3) * GSTAGE;
    const uint32_t bbase = abase + GA_ST;
#pragma unroll
    for (int i = 0; i < 4; i++) {
        const int id = tid + i * 256;
        const int r = id >> 3, c = id & 7;
        CP16(abase + r * 144 + c * 16, A  + (size_t)(m0 + r) * 1024 + t * 64 + c * 8);
        CP16(bbase + r * 144 + c * 16, Bt + (size_t)(n0 + r) * 1024 + t * 64 + c * 8);
    }
    CPCOMMIT();
}

template<int MODE>
__global__ __launch_bounds__(256, 2)
void gemm_h(const __half* __restrict__ A, const __half* __restrict__ Bt,
            const float* __restrict__ bias, float* __restrict__ C, int N,
            __half* __restrict__ oq, __half* __restrict__ ok, __half* __restrict__ ovt)
{
    extern __shared__ uint32_t sw[];
    const uint32_t sb = smem_u32(sw);

    const int tid  = threadIdx.x;
    const int lane = tid & 31;
    const int wid  = tid >> 5;
    const int g    = lane >> 2;
    const int tg   = lane & 3;
    const int warp_m = (wid & 3) * 32;
    const int warp_n = (wid >> 2) * 64;
    const int m0 = blockIdx.y * 128;
    const int n0 = blockIdx.x * 128;

    // ldmatrix per-lane addressing (144 B stride)
    const int lrow = (lane & 7) + ((lane >> 3) & 1) * 8;
    const int lcol = lane >> 4;                       // 0/1
    const uint32_t aOff = (uint32_t)((warp_m + lrow) * 144 + lcol * 16);
    const uint32_t bOff = (uint32_t)((warp_n + lrow) * 144 + lcol * 16);

    float acc[2][8][4];
#pragma unroll
    for (int mt = 0; mt < 2; mt++)
#pragma unroll
        for (int nt = 0; nt < 8; nt++)
#pragma unroll
            for (int i = 0; i < 4; i++) acc[mt][nt][i] = 0.f;

    g_issue64(A, Bt, m0, n0, 0, tid, sb);
    g_issue64(A, Bt, m0, n0, 1, tid, sb);

    for (int t = 0; t < 16; ++t) {
        if (t < 15) { CPWAIT(1); } else { CPWAIT(0); }
        __syncthreads();
        // stage (t+2)%3 was last read at iteration t-1; barrier above proves done
        if (t + 2 < 16) g_issue64(A, Bt, m0, n0, t + 2, tid, sb);

        const uint32_t aS = sb + (t % 3) * GSTAGE;
        const uint32_t bS = aS + GA_ST;

#pragma unroll
        for (int kt = 0; kt < 4; ++kt) {
            uint32_t afr[2][4];
            ldsm4(afr[0], aS + aOff + kt * 32);
            ldsm4(afr[1], aS + aOff + 2304 + kt * 32);       // +16 rows
            uint32_t bfr[4][4];
#pragma unroll
            for (int ntp = 0; ntp < 4; ntp++)
                ldsm4(bfr[ntp], bS + bOff + ntp * 2304 + kt * 32);
#pragma unroll
            for (int mt = 0; mt < 2; mt++)
#pragma unroll
                for (int ntp = 0; ntp < 4; ntp++) {
                    mma16(acc[mt][2*ntp],   afr[mt], bfr[ntp][0], bfr[ntp][2]);
                    mma16(acc[mt][2*ntp+1], afr[mt], bfr[ntp][1], bfr[ntp][3]);
                }
        }
    }

    // epilogue
    const int rowB = m0 + warp_m;
    const int colB = n0 + warp_n;
#pragma unroll
    for (int mt = 0; mt < 2; mt++) {
#pragma unroll
        for (int nt = 0; nt < 8; nt++) {
            const int r = rowB + mt * 16 + g;
            const int c = colB + nt * 8 + 2 * tg;
            const float bv0 = bias[c], bv1 = bias[c + 1];
            const float v00 = acc[mt][nt][0] + bv0;
            const float v01 = acc[mt][nt][1] + bv1;
            const float v10 = acc[mt][nt][2] + bv0;
            const float v11 = acc[mt][nt][3] + bv1;
            if (MODE == 0) {
                const int sel = c >> 10;
                const int cc  = c & 1023;
                const int h   = cc >> 6;
                const int d   = cc & 63;
                const int b0_ = r >> 11,        t0_ = r & 2047;
                const int b1_ = (r + 8) >> 11,  t1_ = (r + 8) & 2047;
                if (sel < 2) {
                    __half* dst = (sel == 0) ? oq : ok;
                    const size_t i0 = (((size_t)(b0_ * NH + h) * SEQ) + t0_) * HD + d;
                    const size_t i1 = (((size_t)(b1_ * NH + h) * SEQ) + t1_) * HD + d;
                    *(uint32_t*)&dst[i0] = pack_h2(v00, v01);
                    *(uint32_t*)&dst[i1] = pack_h2(v10, v11);
                } else {
                    // V transposed: [B,H,D,T]
                    const size_t base0 = ((size_t)(b0_ * NH + h) * HD + d) * SEQ + t0_;
                    const size_t base1 = ((size_t)(b1_ * NH + h) * HD + d) * SEQ + t1_;
                    ovt[base0]       = __float2half_rn(v00);
                    ovt[base0 + SEQ] = __float2half_rn(v01);
                    ovt[base1]       = __float2half_rn(v10);
                    ovt[base1 + SEQ] = __float2half_rn(v11);
                }
            } else {
                *(float2*)&C[(size_t)r * N + c]       = make_float2(v00, v01);
                *(float2*)&C[(size_t)(r + 8) * N + c] = make_float2(v10, v11);
            }
        }
    }
}

// ---------------------------------------------------------------------------
// Flash attention, fp16 m16n8k16, Br=128 x Bc=64, 256 threads (8 warps x 16
// rows), 2 CTAs/SM. FA2-style: P stays in registers; Q pre-scaled by 0.125.
// K [t][d], V transposed [d][t]; smem stride 144 B (LDSM conflict-free).
// (unchanged — passing, near its plateau)
// ---------------------------------------------------------------------------
#define AST 4608                       // words per region: 128*36 (Q) = 2*64*36 (K/V)
#define ASMEM (3 * AST * 4)            // 55296 B -> 2 CTAs/SM

__device__ __forceinline__ void issue_kv(const __half* k, const __half* vt,
                                         int bh, int kb, int buf, int tid,
                                         uint32_t kbase, uint32_t vbase) {
    const __half* ksrc = k  + ((size_t)bh * SEQ + (size_t)kb * 64) * HD;
    const __half* vsrc = vt + (size_t)bh * HD * SEQ + (size_t)kb * 64;
    const uint32_t kb_ = kbase + buf * (64 * 144);
    const uint32_t vb_ = vbase + buf * (64 * 144);
#pragma unroll
    for (int i = 0; i < 2; i++) {
        const int id = tid + i * 256;
        const int r = id >> 3, c = id & 7;
        CP16(kb_ + r * 144 + c * 16, ksrc + (size_t)r * HD + c * 8);
        CP16(vb_ + r * 144 + c * 16, vsrc + (size_t)r * SEQ + c * 8);
    }
    CPCOMMIT();
}

__global__ __launch_bounds__(256, 2)
void attn_h(const __half* __restrict__ q, const __half* __restrict__ k,
            const __half* __restrict__ vt, __half* __restrict__ out)
{
    extern __shared__ uint32_t sw[];
    const uint32_t sb    = smem_u32(sw);
    const uint32_t kbase = sb + AST * 4;
    const uint32_t vbase = sb + 2 * AST * 4;

    const int tid  = threadIdx.x;
    const int lane = tid & 31;
    const int wid  = tid >> 5;
    const int g    = lane >> 2;
    const int tg   = lane & 3;
    const int wbase = wid * 16;

    // ldmatrix per-lane addressing
    const int lrow = (lane & 7) + ((lane >> 3) & 1) * 8;
    const int lcol = lane >> 4;
    const uint32_t qpOff = (uint32_t)((wbase + lrow) * 144 + lcol * 16);
    const uint32_t kvOff = (uint32_t)(lrow * 144 + lcol * 16);

    const int bh = blockIdx.y;
    const int qb = (gridDim.x - 1) - blockIdx.x;   // big tiles first
    const int b_ = bh >> 4;
    const int h  = bh & 15;
    const int nkv = 2 * qb + 2;

    // prologue: G0 = Q + KV0, G1 = KV1
    {
        const __half* qsrc = q + ((size_t)bh * SEQ + (size_t)qb * 128) * HD;
#pragma unroll
        for (int i = 0; i < 4; i++) {
            const int id = tid + i * 256;
            const int r = id >> 3, c = id & 7;
            CP16(sb + r * 144 + c * 16, qsrc + (size_t)r * HD + c * 8);
        }
        const __half* ksrc = k  + (size_t)bh * SEQ * HD;
        const __half* vsrc = vt + (size_t)bh * HD * SEQ;
#pragma unroll
        for (int i = 0; i < 2; i++) {
            const int id = tid + i * 256;
            const int r = id >> 3, c = id & 7;
            CP16(kbase + r * 144 + c * 16, ksrc + (size_t)r * HD + c * 8);
            CP16(vbase + r * 144 + c * 16, vsrc + (size_t)r * SEQ + c * 8);
        }
        CPCOMMIT();
        issue_kv(k, vt, bh, 1, 1, tid, kbase, vbase);
    }
    CPWAIT(1);
    __syncthreads();

    // Q fragments in registers, pre-scaled by 1/sqrt(64)=0.125 (exact in fp16)
    uint32_t qf[4][4];
    {
        const __half2 sc = __half2half2(__float2half_rn(0.125f));
#pragma unroll
        for (int kt = 0; kt < 4; kt++) {
            ldsm4(qf[kt], sb + qpOff + kt * 32);
#pragma unroll
            for (int i = 0; i < 4; i++) {
                __half2 v = *reinterpret_cast<__half2*>(&qf[kt][i]);
                v = __hmul2(v, sc);
                qf[kt][i] = *reinterpret_cast<uint32_t*>(&v);
            }
        }
    }

    float m0 = -INFINITY, m1 = -INFINITY, l0 = 0.f, l1 = 0.f;
    float O[8][4];
#pragma unroll
    for (int nt = 0; nt < 8; nt++)
#pragma unroll
        for (int i = 0; i < 4; i++) O[nt][i] = 0.f;

    for (int kb = 0; kb < nkv; ++kb) {
        if (kb > 0) {
            if (kb + 1 < nkv) { CPWAIT(1); } else { CPWAIT(0); }
            __syncthreads();
        }
        const uint32_t kB = kbase + (kb & 1) * (64 * 144);
        const uint32_t vB = vbase + (kb & 1) * (64 * 144);

        // S = (Q/8) @ K^T
        float s_[8][4];
#pragma unroll
        for (int nt = 0; nt < 8; nt++)
#pragma unroll
            for (int i = 0; i < 4; i++) s_[nt][i] = 0.f;
#pragma unroll
        for (int kt = 0; kt < 4; kt++) {
            uint32_t bfr[4][4];
#pragma unroll
            for (int ntp = 0; ntp < 4; ntp++)
                ldsm4(bfr[ntp], kB + kvOff + ntp * 2304 + kt * 32);  // 16*144
#pragma unroll
            for (int ntp = 0; ntp < 4; ntp++) {
                mma16(s_[2*ntp],   qf[kt], bfr[ntp][0], bfr[ntp][2]);
                mma16(s_[2*ntp+1], qf[kt], bfr[ntp][1], bfr[ntp][3]);
            }
        }

        // causal mask (only in the last two kv tiles)
        if (kb >= 2 * qb) {
            const int rg0 = qb * 128 + wbase + g;
#pragma unroll
            for (int nt = 0; nt < 8; nt++) {
                const int cg = kb * 64 + nt * 8 + 2 * tg;
                if (cg > rg0)         s_[nt][0] = -INFINITY;
                if (cg + 1 > rg0)     s_[nt][1] = -INFINITY;
                if (cg > rg0 + 8)     s_[nt][2] = -INFINITY;
                if (cg + 1 > rg0 + 8) s_[nt][3] = -INFINITY;
            }
        }

        // online softmax
        float mx0 = -INFINITY, mx1 = -INFINITY;
#pragma unroll
        for (int nt = 0; nt < 8; nt++) {
            mx0 = fmaxf(mx0, fmaxf(s_[nt][0], s_[nt][1]));
            mx1 = fmaxf(mx1, fmaxf(s_[nt][2], s_[nt][3]));
        }
#pragma unroll
        for (int off = 1; off < 4; off <<= 1) {
            mx0 = fmaxf(mx0, __shfl_xor_sync(0xffffffffu, mx0, off));
            mx1 = fmaxf(mx1, __shfl_xor_sync(0xffffffffu, mx1, off));
        }
        const float mn0 = fmaxf(m0, mx0);
        const float mn1 = fmaxf(m1, mx1);
        const float al0 = __expf(m0 - mn0);
        const float al1 = __expf(m1 - mn1);
        m0 = mn0; m1 = mn1;

        float rs0 = 0.f, rs1 = 0.f;
#pragma unroll
        for (int nt = 0; nt < 8; nt++) {
            s_[nt][0] = __expf(s_[nt][0] - mn0); rs0 += s_[nt][0];
            s_[nt][1] = __expf(s_[nt][1] - mn0); rs0 += s_[nt][1];
            s_[nt][2] = __expf(s_[nt][2] - mn1); rs1 += s_[nt][2];
            s_[nt][3] = __expf(s_[nt][3] - mn1); rs1 += s_[nt][3];
        }
#pragma unroll
        for (int off = 1; off < 4; off <<= 1) {
            rs0 += __shfl_xor_sync(0xffffffffu, rs0, off);
            rs1 += __shfl_xor_sync(0xffffffffu, rs1, off);
        }
        l0 = l0 * al0 + rs0;
        l1 = l1 * al1 + rs1;
#pragma unroll
        for (int nt = 0; nt < 8; nt++) {
            O[nt][0] *= al0; O[nt][1] *= al0;
            O[nt][2] *= al1; O[nt][3] *= al1;
        }

        // P stays in registers: S C-fragment == PV A-fragment (fp16 packed)
        // O += P @ V   (B = V^T [d][t], k-contiguous)
#pragma unroll
        for (int kt = 0; kt < 4; kt++) {
            uint32_t pa[4];
            pa[0] = pack_h2(s_[2*kt][0],   s_[2*kt][1]);
            pa[1] = pack_h2(s_[2*kt][2],   s_[2*kt][3]);
            pa[2] = pack_h2(s_[2*kt+1][0], s_[2*kt+1][1]);
            pa[3] = pack_h2(s_[2*kt+1][2], s_[2*kt+1][3]);
            uint32_t bfr[4][4];
#pragma unroll
            for (int ntp = 0; ntp < 4; ntp++)
                ldsm4(bfr[ntp], vB + kvOff + ntp * 2304 + kt * 32);
#pragma unroll
            for (int ntp = 0; ntp < 4; ntp++) {
                mma16(O[2*ntp],   pa, bfr[ntp][0], bfr[ntp][2]);
                mma16(O[2*ntp+1], pa, bfr[ntp][1], bfr[ntp][3]);
            }
        }
        __syncthreads();
        if (kb + 2 < nkv) issue_kv(k, vt, bh, kb + 2, kb & 1, tid, kbase, vbase);
    }

    // normalize, write fp16 to g_attn [B*T, C]
    const float inv0 = 1.f / l0;
    const float inv1 = 1.f / l1;
    const int t0 = qb * 128 + wbase + g;
#pragma unroll
    for (int nt = 0; nt < 8; nt++) {
        const int c = h * HD + nt * 8 + 2 * tg;
        *(uint32_t*)&out[((size_t)(b_ * SEQ + t0)) * DIM + c] =
            pack_h2(O[nt][0] * inv0, O[nt][1] * inv0);
        *(uint32_t*)&out[((size_t)(b_ * SEQ + t0 + 8)) * DIM + c] =
            pack_h2(O[nt][2] * inv1, O[nt][3] * inv1);
    }
}

// ---------------------------------------------------------------------------
extern "C" void kernel_launch(void* const* d_in, const int* in_sizes, int n_in,
                              void* d_out, int out_size)
{
    const float* x     = (const float*)d_in[0];
    const float* Wqkv  = (const float*)d_in[1];
    const float* bqkv  = (const float*)d_in[2];
    const float* Wproj = (const float*)d_in[3];
    const float* bproj = (const float*)d_in[4];
    float* out = (float*)d_out;

    __half *gq, *gk, *gvt, *gattn, *gxh, *gwqkvh, *gwprojh;
    cudaGetSymbolAddress((void**)&gq, g_q);
    cudaGetSymbolAddress((void**)&gk, g_k);
    cudaGetSymbolAddress((void**)&gvt, g_vt);
    cudaGetSymbolAddress((void**)&gattn, g_attn);
    cudaGetSymbolAddress((void**)&gxh, g_xh);
    cudaGetSymbolAddress((void**)&gwqkvh, g_wqkvh);
    cudaGetSymbolAddress((void**)&gwprojh, g_wprojh);

    cudaFuncSetAttribute(gemm_h<0>, cudaFuncAttributeMaxDynamicSharedMemorySize, GSMEM);
    cudaFuncSetAttribute(gemm_h<1>, cudaFuncAttributeMaxDynamicSharedMemorySize, GSMEM);
    cudaFuncSetAttribute(attn_h,   cudaFuncAttributeMaxDynamicSharedMemorySize, ASMEM);

    // 0) fp16 pre-convert (x elementwise; weights converted + transposed to [N][K])
    cvt_h_kernel<<<(BT*DIM)/2048, 256>>>(x, gxh, BT*DIM);
    cvt_tr_kernel<<<dim3(QKVN/32, DIM/32), dim3(32, 8)>>>(Wqkv, gwqkvh, DIM, QKVN);
    cvt_tr_kernel<<<dim3(DIM/32, DIM/32), dim3(32, 8)>>>(Wproj, gwprojh, DIM, DIM);

    // 1) QKV projection + head scatter (V transposed)
    {
        dim3 grid(QKVN / 128, BT / 128);   // (24, 32)
        gemm_h<0><<<grid, 256, GSMEM>>>(gxh, gwqkvh, bqkv, nullptr,
                                        QKVN, gq, gk, gvt);
    }
    // 2) Causal flash attention
    {
        dim3 grid(SEQ / 128, BATCH * NH);  // (16, 32)
        attn_h<<<grid, 256, ASMEM>>>(gq, gk, gvt, gattn);
    }
    // 3) Output projection
    {
        dim3 grid(DIM / 128, BT / 128);    // (8, 32)
        gemm_h<1><<<grid, 256, GSMEM>>>(gattn, gwprojh, bproj, out,
                                        DIM, nullptr, nullptr, nullptr);
    }
    (void)in_sizes; (void)n_in; (void)out_size;
}

// round 13
// speedup vs baseline: 1.0257x; 1.0179x over previous
#include <cuda_runtime.h>
#include <cuda_fp16.h>
#include <math.h>
#include <stdint.h>

#define BATCH 2
#define SEQ   2048
#define DIM   1024
#define NH    16
#define HD    64
#define BT    (BATCH*SEQ)      // 4096
#define QKVN  (3*DIM)          // 3072

// Scratch (static device arrays; no allocations allowed)
__device__ __half g_q[BATCH*NH*SEQ*HD];     // [B,H,T,D]
__device__ __half g_k[BATCH*NH*SEQ*HD];     // [B,H,T,D]
__device__ __half g_vt[BATCH*NH*HD*SEQ];    // [B,H,D,T]  (transposed V)
__device__ __half g_attn[BT*DIM];           // [B*T, C]
__device__ __half g_xh[BT*DIM];             // fp16(x)
__device__ __half g_wqkvh[QKVN*DIM];        // fp16(W_qkv^T)  [N][K]
__device__ __half g_wprojh[DIM*DIM];        // fp16(W_proj^T) [N][K]

// ---------------------------------------------------------------------------
__device__ __forceinline__ uint32_t smem_u32(const void* p) {
    uint32_t a;
    asm("{ .reg .u64 t; cvta.to.shared.u64 t, %1; cvt.u32.u64 %0, t; }" : "=r"(a) : "l"(p));
    return a;
}
__device__ __forceinline__ uint32_t pack_h2(float lo, float hi) {
    __half2 h = __floats2half2_rn(lo, hi);
    return *reinterpret_cast<uint32_t*>(&h);
}
#define CP16(dst, src) \
    asm volatile("cp.async.cg.shared.global [%0], [%1], 16;" :: "r"(dst), "l"(src) : "memory")
#define CPCOMMIT() asm volatile("cp.async.commit_group;" ::: "memory")
#define CPWAIT(n)  asm volatile("cp.async.wait_group %0;" :: "n"(n) : "memory")

// m16n8k16 fp16 mma, fp32 accum
__device__ __forceinline__ void mma16(float* c, const uint32_t* a, uint32_t b0, uint32_t b1) {
    asm volatile(
        "mma.sync.aligned.m16n8k16.row.col.f32.f16.f16.f32 "
        "{%0,%1,%2,%3},{%4,%5,%6,%7},{%8,%9},{%0,%1,%2,%3};\n"
        : "+f"(c[0]), "+f"(c[1]), "+f"(c[2]), "+f"(c[3])
        : "r"(a[0]), "r"(a[1]), "r"(a[2]), "r"(a[3]), "r"(b0), "r"(b1));
}

// ldmatrix x4: four 8x8 b16 matrices; lane l supplies row address
__device__ __forceinline__ void ldsm4(uint32_t* r, uint32_t addr) {
    asm volatile("ldmatrix.sync.aligned.m8n8.x4.shared.b16 {%0,%1,%2,%3}, [%4];"
                 : "=r"(r[0]), "=r"(r[1]), "=r"(r[2]), "=r"(r[3]) : "r"(addr));
}

// ---------------------------------------------------------------------------
// pre-convert kernels
// ---------------------------------------------------------------------------
__global__ void cvt_h_kernel(const float* __restrict__ src, __half* __restrict__ dst, int n) {
    int i = (blockIdx.x * 256 + threadIdx.x) * 8;
    if (i < n) {
        float4 v0 = *(const float4*)(src + i);
        float4 v1 = *(const float4*)(src + i + 4);
        uint4 u = { pack_h2(v0.x, v0.y), pack_h2(v0.z, v0.w),
                    pack_h2(v1.x, v1.y), pack_h2(v1.z, v1.w) };
        *(uint4*)(dst + i) = u;
    }
}

// Fused transpose of both weight matrices: [K][N] fp32 -> [N][K] fp16.
// blocks [0, QKVN/32): Wqkv;  blocks [QKVN/32, QKVN/32+DIM/32): Wproj.
__global__ void cvt_tr2_kernel(const float* __restrict__ w1, __half* __restrict__ d1,
                               const float* __restrict__ w2, __half* __restrict__ d2) {
    __shared__ float tile[32][33];
    const int bx = blockIdx.x;
    const float* src;
    __half* dst;
    int N, n0;
    if (bx < QKVN / 32) { src = w1; dst = d1; N = QKVN; n0 = bx * 32; }
    else                { src = w2; dst = d2; N = DIM;  n0 = (bx - QKVN / 32) * 32; }
    const int k0 = blockIdx.y * 32;
    const int tx = threadIdx.x, ty = threadIdx.y;
    for (int i = ty; i < 32; i += 8)
        tile[i][tx] = src[(size_t)(k0 + i) * N + n0 + tx];
    __syncthreads();
    for (int i = ty; i < 32; i += 8)
        dst[(size_t)(n0 + i) * DIM + k0 + tx] = __float2half_rn(tile[tx][i]);
}

// ---------------------------------------------------------------------------
// fp16 GEMM: tile 128x128, BK=64, 3 stages cp.async (CPWAIT(1)), 256 threads,
// 2 CTAs/SM, warp tile 32x64, ldmatrix at 144 B stride. (frozen — r12 best)
// A [M,1024] fp16 row-major; B pre-transposed [N][1024] (k-contiguous).
// MODE 0: QKV scatter (q,k normal; v transposed) ; MODE 1: C = acc + bias.
// ---------------------------------------------------------------------------
#define GA_ST 18432
#define GSTAGE (2 * GA_ST)             // A+B per stage: 36864
#define GSMEM (3 * GSTAGE)             // 110592 B -> 2 CTAs/SM

__device__ __forceinline__ void g_issue64(const __half* A, const __half* Bt,
                                          int m0, int n0, int t, int tid, uint32_t sb) {
    const uint32_t abase = sb + (t % 3) * GSTAGE;
    const uint32_t bbase = abase + GA_ST;
#pragma unroll
    for (int i = 0; i < 4; i++) {
        const int id = tid + i * 256;
        const int r = id >> 3, c = id & 7;
        CP16(abase + r * 144 + c * 16, A  + (size_t)(m0 + r) * 1024 + t * 64 + c * 8);
        CP16(bbase + r * 144 + c * 16, Bt + (size_t)(n0 + r) * 1024 + t * 64 + c * 8);
    }
    CPCOMMIT();
}

template<int MODE>
__global__ __launch_bounds__(256, 2)
void gemm_h(const __half* __restrict__ A, const __half* __restrict__ Bt,
            const float* __restrict__ bias, float* __restrict__ C, int N,
            __half* __restrict__ oq, __half* __restrict__ ok, __half* __restrict__ ovt)
{
    extern __shared__ uint32_t sw[];
    const uint32_t sb = smem_u32(sw);

    const int tid  = threadIdx.x;
    const int lane = tid & 31;
    const int wid  = tid >> 5;
    const int g    = lane >> 2;
    const int tg   = lane & 3;
    const int warp_m = (wid & 3) * 32;
    const int warp_n = (wid >> 2) * 64;
    const int m0 = blockIdx.y * 128;
    const int n0 = blockIdx.x * 128;

    const int lrow = (lane & 7) + ((lane >> 3) & 1) * 8;
    const int lcol = lane >> 4;
    const uint32_t aOff = (uint32_t)((warp_m + lrow) * 144 + lcol * 16);
    const uint32_t bOff = (uint32_t)((warp_n + lrow) * 144 + lcol * 16);

    float acc[2][8][4];
#pragma unroll
    for (int mt = 0; mt < 2; mt++)
#pragma unroll
        for (int nt = 0; nt < 8; nt++)
#pragma unroll
            for (int i = 0; i < 4; i++) acc[mt][nt][i] = 0.f;

    g_issue64(A, Bt, m0, n0, 0, tid, sb);
    g_issue64(A, Bt, m0, n0, 1, tid, sb);

    for (int t = 0; t < 16; ++t) {
        if (t < 15) { CPWAIT(1); } else { CPWAIT(0); }
        __syncthreads();
        if (t + 2 < 16) g_issue64(A, Bt, m0, n0, t + 2, tid, sb);

        const uint32_t aS = sb + (t % 3) * GSTAGE;
        const uint32_t bS = aS + GA_ST;

#pragma unroll
        for (int kt = 0; kt < 4; ++kt) {
            uint32_t afr[2][4];
            ldsm4(afr[0], aS + aOff + kt * 32);
            ldsm4(afr[1], aS + aOff + 2304 + kt * 32);
            uint32_t bfr[4][4];
#pragma unroll
            for (int ntp = 0; ntp < 4; ntp++)
                ldsm4(bfr[ntp], bS + bOff + ntp * 2304 + kt * 32);
#pragma unroll
            for (int mt = 0; mt < 2; mt++)
#pragma unroll
                for (int ntp = 0; ntp < 4; ntp++) {
                    mma16(acc[mt][2*ntp],   afr[mt], bfr[ntp][0], bfr[ntp][2]);
                    mma16(acc[mt][2*ntp+1], afr[mt], bfr[ntp][1], bfr[ntp][3]);
                }
        }
    }

    // epilogue
    const int rowB = m0 + warp_m;
    const int colB = n0 + warp_n;
#pragma unroll
    for (int mt = 0; mt < 2; mt++) {
#pragma unroll
        for (int nt = 0; nt < 8; nt++) {
            const int r = rowB + mt * 16 + g;
            const int c = colB + nt * 8 + 2 * tg;
            const float bv0 = bias[c], bv1 = bias[c + 1];
            const float v00 = acc[mt][nt][0] + bv0;
            const float v01 = acc[mt][nt][1] + bv1;
            const float v10 = acc[mt][nt][2] + bv0;
            const float v11 = acc[mt][nt][3] + bv1;
            if (MODE == 0) {
                const int sel = c >> 10;
                const int cc  = c & 1023;
                const int h   = cc >> 6;
                const int d   = cc & 63;
                const int b0_ = r >> 11,        t0_ = r & 2047;
                const int b1_ = (r + 8) >> 11,  t1_ = (r + 8) & 2047;
                if (sel < 2) {
                    __half* dst = (sel == 0) ? oq : ok;
                    const size_t i0 = (((size_t)(b0_ * NH + h) * SEQ) + t0_) * HD + d;
                    const size_t i1 = (((size_t)(b1_ * NH + h) * SEQ) + t1_) * HD + d;
                    *(uint32_t*)&dst[i0] = pack_h2(v00, v01);
                    *(uint32_t*)&dst[i1] = pack_h2(v10, v11);
                } else {
                    const size_t base0 = ((size_t)(b0_ * NH + h) * HD + d) * SEQ + t0_;
                    const size_t base1 = ((size_t)(b1_ * NH + h) * HD + d) * SEQ + t1_;
                    ovt[base0]       = __float2half_rn(v00);
                    ovt[base0 + SEQ] = __float2half_rn(v01);
                    ovt[base1]       = __float2half_rn(v10);
                    ovt[base1 + SEQ] = __float2half_rn(v11);
                }
            } else {
                *(float2*)&C[(size_t)r * N + c]       = make_float2(v00, v01);
                *(float2*)&C[(size_t)(r + 8) * N + c] = make_float2(v10, v11);
            }
        }
    }
}

// ---------------------------------------------------------------------------
// Flash attention, fp16 m16n8k16, Br=128 x Bc=64, 256 threads, 2 CTAs/SM.
// FA2 register-P; Q pre-scaled 0.125; 3-buffer KV ring -> ONE sync per tile;
// exp2-domain softmax (FFMA+MUFU per element).
// K [t][d], V transposed [d][t]; smem stride 144 B (LDSM conflict-free).
// ---------------------------------------------------------------------------
#define KVBUF 9216                     // 64 rows * 144 B
#define AQ_BYTES 18432                 // Q region: 128 * 144
#define ASMEM (AQ_BYTES + 6 * KVBUF)   // 73728 B -> 2 CTAs/SM

__device__ __forceinline__ void issue_kv(const __half* k, const __half* vt,
                                         int bh, int kb, int buf, int tid,
                                         uint32_t kbase, uint32_t vbase) {
    const __half* ksrc = k  + ((size_t)bh * SEQ + (size_t)kb * 64) * HD;
    const __half* vsrc = vt + (size_t)bh * HD * SEQ + (size_t)kb * 64;
    const uint32_t kb_ = kbase + buf * KVBUF;
    const uint32_t vb_ = vbase + buf * KVBUF;
#pragma unroll
    for (int i = 0; i < 2; i++) {
        const int id = tid + i * 256;
        const int r = id >> 3, c = id & 7;
        CP16(kb_ + r * 144 + c * 16, ksrc + (size_t)r * HD + c * 8);
        CP16(vb_ + r * 144 + c * 16, vsrc + (size_t)r * SEQ + c * 8);
    }
    CPCOMMIT();
}

__global__ __launch_bounds__(256, 2)
void attn_h(const __half* __restrict__ q, const __half* __restrict__ k,
            const __half* __restrict__ vt, __half* __restrict__ out)
{
    extern __shared__ uint32_t sw[];
    const uint32_t sb    = smem_u32(sw);
    const uint32_t kbase = sb + AQ_BYTES;
    const uint32_t vbase = kbase + 3 * KVBUF;

    const int tid  = threadIdx.x;
    const int lane = tid & 31;
    const int wid  = tid >> 5;
    const int g    = lane >> 2;
    const int tg   = lane & 3;
    const int wbase = wid * 16;

    const int lrow = (lane & 7) + ((lane >> 3) & 1) * 8;
    const int lcol = lane >> 4;
    const uint32_t qpOff = (uint32_t)((wbase + lrow) * 144 + lcol * 16);
    const uint32_t kvOff = (uint32_t)(lrow * 144 + lcol * 16);

    const int bh = blockIdx.y;
    const int qb = (gridDim.x - 1) - blockIdx.x;   // big tiles first
    const int b_ = bh >> 4;
    const int h  = bh & 15;
    const int nkv = 2 * qb + 2;

    // prologue: G0 = Q + KV0 (buf 0), G1 = KV1 (buf 1)
    {
        const __half* qsrc = q + ((size_t)bh * SEQ + (size_t)qb * 128) * HD;
#pragma unroll
        for (int i = 0; i < 4; i++) {
            const int id = tid + i * 256;
            const int r = id >> 3, c = id & 7;
            CP16(sb + r * 144 + c * 16, qsrc + (size_t)r * HD + c * 8);
        }
        const __half* ksrc = k  + (size_t)bh * SEQ * HD;
        const __half* vsrc = vt + (size_t)bh * HD * SEQ;
#pragma unroll
        for (int i = 0; i < 2; i++) {
            const int id = tid + i * 256;
            const int r = id >> 3, c = id & 7;
            CP16(kbase + r * 144 + c * 16, ksrc + (size_t)r * HD + c * 8);
            CP16(vbase + r * 144 + c * 16, vsrc + (size_t)r * SEQ + c * 8);
        }
        CPCOMMIT();
        issue_kv(k, vt, bh, 1, 1, tid, kbase, vbase);
    }
    CPWAIT(1);
    __syncthreads();

    // Q fragments in registers, pre-scaled by 1/sqrt(64)=0.125 (exact in fp16)
    uint32_t qf[4][4];
    {
        const __half2 sc = __half2half2(__float2half_rn(0.125f));
#pragma unroll
        for (int kt = 0; kt < 4; kt++) {
            ldsm4(qf[kt], sb + qpOff + kt * 32);
#pragma unroll
            for (int i = 0; i < 4; i++) {
                __half2 v = *reinterpret_cast<__half2*>(&qf[kt][i]);
                v = __hmul2(v, sc);
                qf[kt][i] = *reinterpret_cast<uint32_t*>(&v);
            }
        }
    }

    const float L2E = 1.4426950408889634f;
    float m0 = -INFINITY, m1 = -INFINITY;     // raw-domain running max
    float m0_2 = -INFINITY, m1_2 = -INFINITY; // log2-domain (m * L2E)
    float l0 = 0.f, l1 = 0.f;
    float O[8][4];
#pragma unroll
    for (int nt = 0; nt < 8; nt++)
#pragma unroll
        for (int i = 0; i < 4; i++) O[nt][i] = 0.f;

    for (int kb = 0; kb < nkv; ++kb) {
        if (kb > 0) {
            if (kb + 1 < nkv) { CPWAIT(1); } else { CPWAIT(0); }
            __syncthreads();   // also fences reads of tile kb-1's buffers
        }
        // buffer (kb+2)%3 last held tile kb-1 -> safe to refill after top sync
        if (kb + 2 < nkv) issue_kv(k, vt, bh, kb + 2, (kb + 2) % 3, tid, kbase, vbase);

        const uint32_t kB = kbase + (kb % 3) * KVBUF;
        const uint32_t vB = vbase + (kb % 3) * KVBUF;

        // S = (Q/8) @ K^T
        float s_[8][4];
#pragma unroll
        for (int nt = 0; nt < 8; nt++)
#pragma unroll
            for (int i = 0; i < 4; i++) s_[nt][i] = 0.f;
#pragma unroll
        for (int kt = 0; kt < 4; kt++) {
            uint32_t bfr[4][4];
#pragma unroll
            for (int ntp = 0; ntp < 4; ntp++)
                ldsm4(bfr[ntp], kB + kvOff + ntp * 2304 + kt * 32);
#pragma unroll
            for (int ntp = 0; ntp < 4; ntp++) {
                mma16(s_[2*ntp],   qf[kt], bfr[ntp][0], bfr[ntp][2]);
                mma16(s_[2*ntp+1], qf[kt], bfr[ntp][1], bfr[ntp][3]);
            }
        }

        // causal mask (only in the last two kv tiles)
        if (kb >= 2 * qb) {
            const int rg0 = qb * 128 + wbase + g;
#pragma unroll
            for (int nt = 0; nt < 8; nt++) {
                const int cg = kb * 64 + nt * 8 + 2 * tg;
                if (cg > rg0)         s_[nt][0] = -INFINITY;
                if (cg + 1 > rg0)     s_[nt][1] = -INFINITY;
                if (cg > rg0 + 8)     s_[nt][2] = -INFINITY;
                if (cg + 1 > rg0 + 8) s_[nt][3] = -INFINITY;
            }
        }

        // online softmax (log2 domain)
        float mx0 = -INFINITY, mx1 = -INFINITY;
#pragma unroll
        for (int nt = 0; nt < 8; nt++) {
            mx0 = fmaxf(mx0, fmaxf(s_[nt][0], s_[nt][1]));
            mx1 = fmaxf(mx1, fmaxf(s_[nt][2], s_[nt][3]));
        }
#pragma unroll
        for (int off = 1; off < 4; off <<= 1) {
            mx0 = fmaxf(mx0, __shfl_xor_sync(0xffffffffu, mx0, off));
            mx1 = fmaxf(mx1, __shfl_xor_sync(0xffffffffu, mx1, off));
        }
        const float mn0 = fmaxf(m0, mx0);
        const float mn1 = fmaxf(m1, mx1);
        const float mn0_2 = mn0 * L2E;
        const float mn1_2 = mn1 * L2E;
        const float al0 = exp2f(m0_2 - mn0_2);
        const float al1 = exp2f(m1_2 - mn1_2);
        m0 = mn0; m1 = mn1; m0_2 = mn0_2; m1_2 = mn1_2;
        const float nm0 = -mn0_2, nm1 = -mn1_2;

        float rs0 = 0.f, rs1 = 0.f;
#pragma unroll
        for (int nt = 0; nt < 8; nt++) {
            s_[nt][0] = exp2f(fmaf(s_[nt][0], L2E, nm0)); rs0 += s_[nt][0];
            s_[nt][1] = exp2f(fmaf(s_[nt][1], L2E, nm0)); rs0 += s_[nt][1];
            s_[nt][2] = exp2f(fmaf(s_[nt][2], L2E, nm1)); rs1 += s_[nt][2];
            s_[nt][3] = exp2f(fmaf(s_[nt][3], L2E, nm1)); rs1 += s_[nt][3];
        }
#pragma unroll
        for (int off = 1; off < 4; off <<= 1) {
            rs0 += __shfl_xor_sync(0xffffffffu, rs0, off);
            rs1 += __shfl_xor_sync(0xffffffffu, rs1, off);
        }
        l0 = l0 * al0 + rs0;
        l1 = l1 * al1 + rs1;
#pragma unroll
        for (int nt = 0; nt < 8; nt++) {
            O[nt][0] *= al0; O[nt][1] *= al0;
            O[nt][2] *= al1; O[nt][3] *= al1;
        }

        // P stays in registers: S C-fragment == PV A-fragment (fp16 packed)
#pragma unroll
        for (int kt = 0; kt < 4; kt++) {
            uint32_t pa[4];
            pa[0] = pack_h2(s_[2*kt][0],   s_[2*kt][1]);
            pa[1] = pack_h2(s_[2*kt][2],   s_[2*kt][3]);
            pa[2] = pack_h2(s_[2*kt+1][0], s_[2*kt+1][1]);
            pa[3] = pack_h2(s_[2*kt+1][2], s_[2*kt+1][3]);
            uint32_t bfr[4][4];
#pragma unroll
            for (int ntp = 0; ntp < 4; ntp++)
                ldsm4(bfr[ntp], vB + kvOff + ntp * 2304 + kt * 32);
#pragma unroll
            for (int ntp = 0; ntp < 4; ntp++) {
                mma16(O[2*ntp],   pa, bfr[ntp][0], bfr[ntp][2]);
                mma16(O[2*ntp+1], pa, bfr[ntp][1], bfr[ntp][3]);
            }
        }
        // no bottom sync: 3-buffer ring defers the reuse guard to next top sync
    }

    // normalize, write fp16 to g_attn [B*T, C]
    const float inv0 = 1.f / l0;
    const float inv1 = 1.f / l1;
    const int t0 = qb * 128 + wbase + g;
#pragma unroll
    for (int nt = 0; nt < 8; nt++) {
        const int c = h * HD + nt * 8 + 2 * tg;
        *(uint32_t*)&out[((size_t)(b_ * SEQ + t0)) * DIM + c] =
            pack_h2(O[nt][0] * inv0, O[nt][1] * inv0);
        *(uint32_t*)&out[((size_t)(b_ * SEQ + t0 + 8)) * DIM + c] =
            pack_h2(O[nt][2] * inv1, O[nt][3] * inv1);
    }
}

// ---------------------------------------------------------------------------
extern "C" void kernel_launch(void* const* d_in, const int* in_sizes, int n_in,
                              void* d_out, int out_size)
{
    const float* x     = (const float*)d_in[0];
    const float* Wqkv  = (const float*)d_in[1];
    const float* bqkv  = (const float*)d_in[2];
    const float* Wproj = (const float*)d_in[3];
    const float* bproj = (const float*)d_in[4];
    float* out = (float*)d_out;

    __half *gq, *gk, *gvt, *gattn, *gxh, *gwqkvh, *gwprojh;
    cudaGetSymbolAddress((void**)&gq, g_q);
    cudaGetSymbolAddress((void**)&gk, g_k);
    cudaGetSymbolAddress((void**)&gvt, g_vt);
    cudaGetSymbolAddress((void**)&gattn, g_attn);
    cudaGetSymbolAddress((void**)&gxh, g_xh);
    cudaGetSymbolAddress((void**)&gwqkvh, g_wqkvh);
    cudaGetSymbolAddress((void**)&gwprojh, g_wprojh);

    cudaFuncSetAttribute(gemm_h<0>, cudaFuncAttributeMaxDynamicSharedMemorySize, GSMEM);
    cudaFuncSetAttribute(gemm_h<1>, cudaFuncAttributeMaxDynamicSharedMemorySize, GSMEM);
    cudaFuncSetAttribute(attn_h,   cudaFuncAttributeMaxDynamicSharedMemorySize, ASMEM);

    // 0) fp16 pre-convert: x elementwise; both weights transposed in one launch
    cvt_h_kernel<<<(BT*DIM)/2048, 256>>>(x, gxh, BT*DIM);
    cvt_tr2_kernel<<<dim3(QKVN/32 + DIM/32, DIM/32), dim3(32, 8)>>>(
        Wqkv, gwqkvh, Wproj, gwprojh);

    // 1) QKV projection + head scatter (V transposed)
    {
        dim3 grid(QKVN / 128, BT / 128);   // (24, 32)
        gemm_h<0><<<grid, 256, GSMEM>>>(gxh, gwqkvh, bqkv, nullptr,
                                        QKVN, gq, gk, gvt);
    }
    // 2) Causal flash attention
    {
        dim3 grid(SEQ / 128, BATCH * NH);  // (16, 32)
        attn_h<<<grid, 256, ASMEM>>>(gq, gk, gvt, gattn);
    }
    // 3) Output projection
    {
        dim3 grid(DIM / 128, BT / 128);    // (8, 32)
        gemm_h<1><<<grid, 256, GSMEM>>>(gattn, gwprojh, bproj, out,
                                        DIM, nullptr, nullptr, nullptr);
    }
    (void)in_sizes; (void)n_in; (void)out_size;
}

// round 14
// speedup vs baseline: 1.0300x; 1.0042x over previous
#include <cuda_runtime.h>
#include <cuda_fp16.h>
#include <math.h>
#include <stdint.h>

#define BATCH 2
#define SEQ   2048
#define DIM   1024
#define NH    16
#define HD    64
#define BT    (BATCH*SEQ)      // 4096
#define QKVN  (3*DIM)          // 3072

// Scratch (static device arrays; no allocations allowed)
__device__ __half g_q[BATCH*NH*SEQ*HD];     // [B,H,T,D]
__device__ __half g_k[BATCH*NH*SEQ*HD];     // [B,H,T,D]
__device__ __half g_vt[BATCH*NH*HD*SEQ];    // [B,H,D,T]  (transposed V)
__device__ __half g_attn[BT*DIM];           // [B*T, C]
__device__ __half g_xh[BT*DIM];             // fp16(x)
__device__ __half g_wqkvh[QKVN*DIM];        // fp16(W_qkv^T)  [N][K]
__device__ __half g_wprojh[DIM*DIM];        // fp16(W_proj^T) [N][K]

// ---------------------------------------------------------------------------
__device__ __forceinline__ uint32_t smem_u32(const void* p) {
    uint32_t a;
    asm("{ .reg .u64 t; cvta.to.shared.u64 t, %1; cvt.u32.u64 %0, t; }" : "=r"(a) : "l"(p));
    return a;
}
__device__ __forceinline__ uint32_t pack_h2(float lo, float hi) {
    __half2 h = __floats2half2_rn(lo, hi);
    return *reinterpret_cast<uint32_t*>(&h);
}
#define CP16(dst, src) \
    asm volatile("cp.async.cg.shared.global [%0], [%1], 16;" :: "r"(dst), "l"(src) : "memory")
#define CPCOMMIT() asm volatile("cp.async.commit_group;" ::: "memory")
#define CPWAIT(n)  asm volatile("cp.async.wait_group %0;" :: "n"(n) : "memory")

// m16n8k16 fp16 mma, fp32 accum
__device__ __forceinline__ void mma16(float* c, const uint32_t* a, uint32_t b0, uint32_t b1) {
    asm volatile(
        "mma.sync.aligned.m16n8k16.row.col.f32.f16.f16.f32 "
        "{%0,%1,%2,%3},{%4,%5,%6,%7},{%8,%9},{%0,%1,%2,%3};\n"
        : "+f"(c[0]), "+f"(c[1]), "+f"(c[2]), "+f"(c[3])
        : "r"(a[0]), "r"(a[1]), "r"(a[2]), "r"(a[3]), "r"(b0), "r"(b1));
}

// ldmatrix x4: four 8x8 b16 matrices; lane l supplies row address
__device__ __forceinline__ void ldsm4(uint32_t* r, uint32_t addr) {
    asm volatile("ldmatrix.sync.aligned.m8n8.x4.shared.b16 {%0,%1,%2,%3}, [%4];"
                 : "=r"(r[0]), "=r"(r[1]), "=r"(r[2]), "=r"(r[3]) : "r"(addr));
}

// ---------------------------------------------------------------------------
// pre-convert kernels
// ---------------------------------------------------------------------------
__global__ void cvt_h_kernel(const float* __restrict__ src, __half* __restrict__ dst, int n) {
    int i = (blockIdx.x * 256 + threadIdx.x) * 8;
    if (i < n) {
        float4 v0 = *(const float4*)(src + i);
        float4 v1 = *(const float4*)(src + i + 4);
        uint4 u = { pack_h2(v0.x, v0.y), pack_h2(v0.z, v0.w),
                    pack_h2(v1.x, v1.y), pack_h2(v1.z, v1.w) };
        *(uint4*)(dst + i) = u;
    }
}

// Fused transpose of both weight matrices: [K][N] fp32 -> [N][K] fp16.
__global__ void cvt_tr2_kernel(const float* __restrict__ w1, __half* __restrict__ d1,
                               const float* __restrict__ w2, __half* __restrict__ d2) {
    __shared__ float tile[32][33];
    const int bx = blockIdx.x;
    const float* src;
    __half* dst;
    int N, n0;
    if (bx < QKVN / 32) { src = w1; dst = d1; N = QKVN; n0 = bx * 32; }
    else                { src = w2; dst = d2; N = DIM;  n0 = (bx - QKVN / 32) * 32; }
    const int k0 = blockIdx.y * 32;
    const int tx = threadIdx.x, ty = threadIdx.y;
    for (int i = ty; i < 32; i += 8)
        tile[i][tx] = src[(size_t)(k0 + i) * N + n0 + tx];
    __syncthreads();
    for (int i = ty; i < 32; i += 8)
        dst[(size_t)(n0 + i) * DIM + k0 + tx] = __float2half_rn(tile[tx][i]);
}

// ---------------------------------------------------------------------------
// fp16 GEMM: tile 128x128, BK=64, 3 stages cp.async (CPWAIT(1)), 256 threads,
// 2 CTAs/SM, warp tile 32x64, ldmatrix at 144 B stride. (frozen — r12 best)
// ---------------------------------------------------------------------------
#define GA_ST 18432
#define GSTAGE (2 * GA_ST)             // A+B per stage: 36864
#define GSMEM (3 * GSTAGE)             // 110592 B -> 2 CTAs/SM

__device__ __forceinline__ void g_issue64(const __half* A, const __half* Bt,
                                          int m0, int n0, int t, int tid, uint32_t sb) {
    const uint32_t abase = sb + (t % 3) * GSTAGE;
    const uint32_t bbase = abase + GA_ST;
#pragma unroll
    for (int i = 0; i < 4; i++) {
        const int id = tid + i * 256;
        const int r = id >> 3, c = id & 7;
        CP16(abase + r * 144 + c * 16, A  + (size_t)(m0 + r) * 1024 + t * 64 + c * 8);
        CP16(bbase + r * 144 + c * 16, Bt + (size_t)(n0 + r) * 1024 + t * 64 + c * 8);
    }
    CPCOMMIT();
}

template<int MODE>
__global__ __launch_bounds__(256, 2)
void gemm_h(const __half* __restrict__ A, const __half* __restrict__ Bt,
            const float* __restrict__ bias, float* __restrict__ C, int N,
            __half* __restrict__ oq, __half* __restrict__ ok, __half* __restrict__ ovt)
{
    extern __shared__ uint32_t sw[];
    const uint32_t sb = smem_u32(sw);

    const int tid  = threadIdx.x;
    const int lane = tid & 31;
    const int wid  = tid >> 5;
    const int g    = lane >> 2;
    const int tg   = lane & 3;
    const int warp_m = (wid & 3) * 32;
    const int warp_n = (wid >> 2) * 64;
    const int m0 = blockIdx.y * 128;
    const int n0 = blockIdx.x * 128;

    const int lrow = (lane & 7) + ((lane >> 3) & 1) * 8;
    const int lcol = lane >> 4;
    const uint32_t aOff = (uint32_t)((warp_m + lrow) * 144 + lcol * 16);
    const uint32_t bOff = (uint32_t)((warp_n + lrow) * 144 + lcol * 16);

    float acc[2][8][4];
#pragma unroll
    for (int mt = 0; mt < 2; mt++)
#pragma unroll
        for (int nt = 0; nt < 8; nt++)
#pragma unroll
            for (int i = 0; i < 4; i++) acc[mt][nt][i] = 0.f;

    g_issue64(A, Bt, m0, n0, 0, tid, sb);
    g_issue64(A, Bt, m0, n0, 1, tid, sb);

    for (int t = 0; t < 16; ++t) {
        if (t < 15) { CPWAIT(1); } else { CPWAIT(0); }
        __syncthreads();
        if (t + 2 < 16) g_issue64(A, Bt, m0, n0, t + 2, tid, sb);

        const uint32_t aS = sb + (t % 3) * GSTAGE;
        const uint32_t bS = aS + GA_ST;

#pragma unroll
        for (int kt = 0; kt < 4; ++kt) {
            uint32_t afr[2][4];
            ldsm4(afr[0], aS + aOff + kt * 32);
            ldsm4(afr[1], aS + aOff + 2304 + kt * 32);
            uint32_t bfr[4][4];
#pragma unroll
            for (int ntp = 0; ntp < 4; ntp++)
                ldsm4(bfr[ntp], bS + bOff + ntp * 2304 + kt * 32);
#pragma unroll
            for (int mt = 0; mt < 2; mt++)
#pragma unroll
                for (int ntp = 0; ntp < 4; ntp++) {
                    mma16(acc[mt][2*ntp],   afr[mt], bfr[ntp][0], bfr[ntp][2]);
                    mma16(acc[mt][2*ntp+1], afr[mt], bfr[ntp][1], bfr[ntp][3]);
                }
        }
    }

    // epilogue
    const int rowB = m0 + warp_m;
    const int colB = n0 + warp_n;
#pragma unroll
    for (int mt = 0; mt < 2; mt++) {
#pragma unroll
        for (int nt = 0; nt < 8; nt++) {
            const int r = rowB + mt * 16 + g;
            const int c = colB + nt * 8 + 2 * tg;
            const float bv0 = bias[c], bv1 = bias[c + 1];
            const float v00 = acc[mt][nt][0] + bv0;
            const float v01 = acc[mt][nt][1] + bv1;
            const float v10 = acc[mt][nt][2] + bv0;
            const float v11 = acc[mt][nt][3] + bv1;
            if (MODE == 0) {
                const int sel = c >> 10;
                const int cc  = c & 1023;
                const int h   = cc >> 6;
                const int d   = cc & 63;
                const int b0_ = r >> 11,        t0_ = r & 2047;
                const int b1_ = (r + 8) >> 11,  t1_ = (r + 8) & 2047;
                if (sel < 2) {
                    __half* dst = (sel == 0) ? oq : ok;
                    const size_t i0 = (((size_t)(b0_ * NH + h) * SEQ) + t0_) * HD + d;
                    const size_t i1 = (((size_t)(b1_ * NH + h) * SEQ) + t1_) * HD + d;
                    *(uint32_t*)&dst[i0] = pack_h2(v00, v01);
                    *(uint32_t*)&dst[i1] = pack_h2(v10, v11);
                } else {
                    const size_t base0 = ((size_t)(b0_ * NH + h) * HD + d) * SEQ + t0_;
                    const size_t base1 = ((size_t)(b1_ * NH + h) * HD + d) * SEQ + t1_;
                    ovt[base0]       = __float2half_rn(v00);
                    ovt[base0 + SEQ] = __float2half_rn(v01);
                    ovt[base1]       = __float2half_rn(v10);
                    ovt[base1 + SEQ] = __float2half_rn(v11);
                }
            } else {
                *(float2*)&C[(size_t)r * N + c]       = make_float2(v00, v01);
                *(float2*)&C[(size_t)(r + 8) * N + c] = make_float2(v10, v11);
            }
        }
    }
}

// ---------------------------------------------------------------------------
// Flash attention, fp16 m16n8k16, Br=128 x Bc=64, 256 threads, 2 CTAs/SM.
// FA2 register-P; Q pre-scaled 0.125; 3-buffer KV ring (one sync/tile);
// exp2-domain softmax; ROW SUM VIA TENSOR CORE (P @ ones) — removes the
// per-tile FADD+SHFL sum-reduction chain.
// ---------------------------------------------------------------------------
#define KVBUF 9216                     // 64 rows * 144 B
#define AQ_BYTES 18432                 // Q region: 128 * 144
#define ASMEM (AQ_BYTES + 6 * KVBUF)   // 73728 B -> 2 CTAs/SM

__device__ __forceinline__ void issue_kv(const __half* k, const __half* vt,
                                         int bh, int kb, int buf, int tid,
                                         uint32_t kbase, uint32_t vbase) {
    const __half* ksrc = k  + ((size_t)bh * SEQ + (size_t)kb * 64) * HD;
    const __half* vsrc = vt + (size_t)bh * HD * SEQ + (size_t)kb * 64;
    const uint32_t kb_ = kbase + buf * KVBUF;
    const uint32_t vb_ = vbase + buf * KVBUF;
#pragma unroll
    for (int i = 0; i < 2; i++) {
        const int id = tid + i * 256;
        const int r = id >> 3, c = id & 7;
        CP16(kb_ + r * 144 + c * 16, ksrc + (size_t)r * HD + c * 8);
        CP16(vb_ + r * 144 + c * 16, vsrc + (size_t)r * SEQ + c * 8);
    }
    CPCOMMIT();
}

__global__ __launch_bounds__(256, 2)
void attn_h(const __half* __restrict__ q, const __half* __restrict__ k,
            const __half* __restrict__ vt, __half* __restrict__ out)
{
    extern __shared__ uint32_t sw[];
    const uint32_t sb    = smem_u32(sw);
    const uint32_t kbase = sb + AQ_BYTES;
    const uint32_t vbase = kbase + 3 * KVBUF;

    const int tid  = threadIdx.x;
    const int lane = tid & 31;
    const int wid  = tid >> 5;
    const int g    = lane >> 2;
    const int tg   = lane & 3;
    const int wbase = wid * 16;

    const int lrow = (lane & 7) + ((lane >> 3) & 1) * 8;
    const int lcol = lane >> 4;
    const uint32_t qpOff = (uint32_t)((wbase + lrow) * 144 + lcol * 16);
    const uint32_t kvOff = (uint32_t)(lrow * 144 + lcol * 16);

    const int bh = blockIdx.y;
    const int qb = (gridDim.x - 1) - blockIdx.x;   // big tiles first
    const int b_ = bh >> 4;
    const int h  = bh & 15;
    const int nkv = 2 * qb + 2;
    const uint32_t ONES2 = 0x3C003C00u;            // (1.0h, 1.0h)

    // prologue: G0 = Q + KV0 (buf 0), G1 = KV1 (buf 1)
    {
        const __half* qsrc = q + ((size_t)bh * SEQ + (size_t)qb * 128) * HD;
#pragma unroll
        for (int i = 0; i < 4; i++) {
            const int id = tid + i * 256;
            const int r = id >> 3, c = id & 7;
            CP16(sb + r * 144 + c * 16, qsrc + (size_t)r * HD + c * 8);
        }
        const __half* ksrc = k  + (size_t)bh * SEQ * HD;
        const __half* vsrc = vt + (size_t)bh * HD * SEQ;
#pragma unroll
        for (int i = 0; i < 2; i++) {
            const int id = tid + i * 256;
            const int r = id >> 3, c = id & 7;
            CP16(kbase + r * 144 + c * 16, ksrc + (size_t)r * HD + c * 8);
            CP16(vbase + r * 144 + c * 16, vsrc + (size_t)r * SEQ + c * 8);
        }
        CPCOMMIT();
        issue_kv(k, vt, bh, 1, 1, tid, kbase, vbase);
    }
    CPWAIT(1);
    __syncthreads();

    // Q fragments in registers, pre-scaled by 1/sqrt(64)=0.125 (exact in fp16)
    uint32_t qf[4][4];
    {
        const __half2 sc = __half2half2(__float2half_rn(0.125f));
#pragma unroll
        for (int kt = 0; kt < 4; kt++) {
            ldsm4(qf[kt], sb + qpOff + kt * 32);
#pragma unroll
            for (int i = 0; i < 4; i++) {
                __half2 v = *reinterpret_cast<__half2*>(&qf[kt][i]);
                v = __hmul2(v, sc);
                qf[kt][i] = *reinterpret_cast<uint32_t*>(&v);
            }
        }
    }

    const float L2E = 1.4426950408889634f;
    float m0 = -INFINITY, m1 = -INFINITY;     // raw-domain running max
    float m0_2 = -INFINITY, m1_2 = -INFINITY; // log2-domain (m * L2E)
    float l0 = 0.f, l1 = 0.f;
    float O[8][4];
#pragma unroll
    for (int nt = 0; nt < 8; nt++)
#pragma unroll
        for (int i = 0; i < 4; i++) O[nt][i] = 0.f;

    for (int kb = 0; kb < nkv; ++kb) {
        if (kb > 0) {
            if (kb + 1 < nkv) { CPWAIT(1); } else { CPWAIT(0); }
            __syncthreads();   // also fences reads of tile kb-1's buffers
        }
        if (kb + 2 < nkv) issue_kv(k, vt, bh, kb + 2, (kb + 2) % 3, tid, kbase, vbase);

        const uint32_t kB = kbase + (kb % 3) * KVBUF;
        const uint32_t vB = vbase + (kb % 3) * KVBUF;

        // S = (Q/8) @ K^T
        float s_[8][4];
#pragma unroll
        for (int nt = 0; nt < 8; nt++)
#pragma unroll
            for (int i = 0; i < 4; i++) s_[nt][i] = 0.f;
#pragma unroll
        for (int kt = 0; kt < 4; kt++) {
            uint32_t bfr[4][4];
#pragma unroll
            for (int ntp = 0; ntp < 4; ntp++)
                ldsm4(bfr[ntp], kB + kvOff + ntp * 2304 + kt * 32);
#pragma unroll
            for (int ntp = 0; ntp < 4; ntp++) {
                mma16(s_[2*ntp],   qf[kt], bfr[ntp][0], bfr[ntp][2]);
                mma16(s_[2*ntp+1], qf[kt], bfr[ntp][1], bfr[ntp][3]);
            }
        }

        // causal mask (only in the last two kv tiles)
        if (kb >= 2 * qb) {
            const int rg0 = qb * 128 + wbase + g;
#pragma unroll
            for (int nt = 0; nt < 8; nt++) {
                const int cg = kb * 64 + nt * 8 + 2 * tg;
                if (cg > rg0)         s_[nt][0] = -INFINITY;
                if (cg + 1 > rg0)     s_[nt][1] = -INFINITY;
                if (cg > rg0 + 8)     s_[nt][2] = -INFINITY;
                if (cg + 1 > rg0 + 8) s_[nt][3] = -INFINITY;
            }
        }

        // online softmax (log2 domain); row max via quad shuffle
        float mx0 = -INFINITY, mx1 = -INFINITY;
#pragma unroll
        for (int nt = 0; nt < 8; nt++) {
            mx0 = fmaxf(mx0, fmaxf(s_[nt][0], s_[nt][1]));
            mx1 = fmaxf(mx1, fmaxf(s_[nt][2], s_[nt][3]));
        }
#pragma unroll
        for (int off = 1; off < 4; off <<= 1) {
            mx0 = fmaxf(mx0, __shfl_xor_sync(0xffffffffu, mx0, off));
            mx1 = fmaxf(mx1, __shfl_xor_sync(0xffffffffu, mx1, off));
        }
        const float mn0 = fmaxf(m0, mx0);
        const float mn1 = fmaxf(m1, mx1);
        const float mn0_2 = mn0 * L2E;
        const float mn1_2 = mn1 * L2E;
        const float al0 = exp2f(m0_2 - mn0_2);
        const float al1 = exp2f(m1_2 - mn1_2);
        m0 = mn0; m1 = mn1; m0_2 = mn0_2; m1_2 = mn1_2;
        const float nm0 = -mn0_2, nm1 = -mn1_2;

        // exponentiate (no scalar sum — row sum comes from the MMA below)
#pragma unroll
        for (int nt = 0; nt < 8; nt++) {
            s_[nt][0] = exp2f(fmaf(s_[nt][0], L2E, nm0));
            s_[nt][1] = exp2f(fmaf(s_[nt][1], L2E, nm0));
            s_[nt][2] = exp2f(fmaf(s_[nt][2], L2E, nm1));
            s_[nt][3] = exp2f(fmaf(s_[nt][3], L2E, nm1));
        }
#pragma unroll
        for (int nt = 0; nt < 8; nt++) {
            O[nt][0] *= al0; O[nt][1] *= al0;
            O[nt][2] *= al1; O[nt][3] *= al1;
        }

        // P stays in registers; O += P @ V and lsum += P @ ones (tensor core)
        float lsum[4] = {0.f, 0.f, 0.f, 0.f};
#pragma unroll
        for (int kt = 0; kt < 4; kt++) {
            uint32_t pa[4];
            pa[0] = pack_h2(s_[2*kt][0],   s_[2*kt][1]);
            pa[1] = pack_h2(s_[2*kt][2],   s_[2*kt][3]);
            pa[2] = pack_h2(s_[2*kt+1][0], s_[2*kt+1][1]);
            pa[3] = pack_h2(s_[2*kt+1][2], s_[2*kt+1][3]);
            uint32_t bfr[4][4];
#pragma unroll
            for (int ntp = 0; ntp < 4; ntp++)
                ldsm4(bfr[ntp], vB + kvOff + ntp * 2304 + kt * 32);
#pragma unroll
            for (int ntp = 0; ntp < 4; ntp++) {
                mma16(O[2*ntp],   pa, bfr[ntp][0], bfr[ntp][2]);
                mma16(O[2*ntp+1], pa, bfr[ntp][1], bfr[ntp][3]);
            }
            mma16(lsum, pa, ONES2, ONES2);   // row sums (quad-wide via k-reduce)
        }
        l0 = l0 * al0 + lsum[0];
        l1 = l1 * al1 + lsum[2];
        // no bottom sync: 3-buffer ring defers the reuse guard to next top sync
    }

    // normalize, write fp16 to g_attn [B*T, C]
    const float inv0 = 1.f / l0;
    const float inv1 = 1.f / l1;
    const int t0 = qb * 128 + wbase + g;
#pragma unroll
    for (int nt = 0; nt < 8; nt++) {
        const int c = h * HD + nt * 8 + 2 * tg;
        *(uint32_t*)&out[((size_t)(b_ * SEQ + t0)) * DIM + c] =
            pack_h2(O[nt][0] * inv0, O[nt][1] * inv0);
        *(uint32_t*)&out[((size_t)(b_ * SEQ + t0 + 8)) * DIM + c] =
            pack_h2(O[nt][2] * inv1, O[nt][3] * inv1);
    }
}

// ---------------------------------------------------------------------------
extern "C" void kernel_launch(void* const* d_in, const int* in_sizes, int n_in,
                              void* d_out, int out_size)
{
    const float* x     = (const float*)d_in[0];
    const float* Wqkv  = (const float*)d_in[1];
    const float* bqkv  = (const float*)d_in[2];
    const float* Wproj = (const float*)d_in[3];
    const float* bproj = (const float*)d_in[4];
    float* out = (float*)d_out;

    __half *gq, *gk, *gvt, *gattn, *gxh, *gwqkvh, *gwprojh;
    cudaGetSymbolAddress((void**)&gq, g_q);
    cudaGetSymbolAddress((void**)&gk, g_k);
    cudaGetSymbolAddress((void**)&gvt, g_vt);
    cudaGetSymbolAddress((void**)&gattn, g_attn);
    cudaGetSymbolAddress((void**)&gxh, g_xh);
    cudaGetSymbolAddress((void**)&gwqkvh, g_wqkvh);
    cudaGetSymbolAddress((void**)&gwprojh, g_wprojh);

    cudaFuncSetAttribute(gemm_h<0>, cudaFuncAttributeMaxDynamicSharedMemorySize, GSMEM);
    cudaFuncSetAttribute(gemm_h<1>, cudaFuncAttributeMaxDynamicSharedMemorySize, GSMEM);
    cudaFuncSetAttribute(attn_h,   cudaFuncAttributeMaxDynamicSharedMemorySize, ASMEM);

    // 0) fp16 pre-convert: x elementwise; both weights transposed in one launch
    cvt_h_kernel<<<(BT*DIM)/2048, 256>>>(x, gxh, BT*DIM);
    cvt_tr2_kernel<<<dim3(QKVN/32 + DIM/32, DIM/32), dim3(32, 8)>>>(
        Wqkv, gwqkvh, Wproj, gwprojh);

    // 1) QKV projection + head scatter (V transposed)
    {
        dim3 grid(QKVN / 128, BT / 128);   // (24, 32)
        gemm_h<0><<<grid, 256, GSMEM>>>(gxh, gwqkvh, bqkv, nullptr,
                                        QKVN, gq, gk, gvt);
    }
    // 2) Causal flash attention
    {
        dim3 grid(SEQ / 128, BATCH * NH);  // (16, 32)
        attn_h<<<grid, 256, ASMEM>>>(gq, gk, gvt, gattn);
    }
    // 3) Output projection
    {
        dim3 grid(DIM / 128, BT / 128);    // (8, 32)
        gemm_h<1><<<grid, 256, GSMEM>>>(gattn, gwprojh, bproj, out,
                                        DIM, nullptr, nullptr, nullptr);
    }
    (void)in_sizes; (void)n_in; (void)out_size;
}

// round 15
// speedup vs baseline: 1.0329x; 1.0028x over previous
#include <cuda_runtime.h>
#include <cuda_fp16.h>
#include <math.h>
#include <stdint.h>

#define BATCH 2
#define SEQ   2048
#define DIM   1024
#define NH    16
#define HD    64
#define BT    (BATCH*SEQ)      // 4096
#define QKVN  (3*DIM)          // 3072

// Scratch (static device arrays; no allocations allowed)
__device__ __half g_q[BATCH*NH*SEQ*HD];     // [B,H,T,D]
__device__ __half g_k[BATCH*NH*SEQ*HD];     // [B,H,T,D]
__device__ __half g_vt[BATCH*NH*HD*SEQ];    // [B,H,D,T]  (transposed V)
__device__ __half g_attn[BT*DIM];           // [B*T, C]
__device__ __half g_xh[BT*DIM];             // fp16(x)
__device__ __half g_wqkvh[QKVN*DIM];        // fp16(W_qkv^T)  [N][K]
__device__ __half g_wprojh[DIM*DIM];        // fp16(W_proj^T) [N][K]

// ---------------------------------------------------------------------------
__device__ __forceinline__ uint32_t smem_u32(const void* p) {
    uint32_t a;
    asm("{ .reg .u64 t; cvta.to.shared.u64 t, %1; cvt.u32.u64 %0, t; }" : "=r"(a) : "l"(p));
    return a;
}
__device__ __forceinline__ uint32_t pack_h2(float lo, float hi) {
    __half2 h = __floats2half2_rn(lo, hi);
    return *reinterpret_cast<uint32_t*>(&h);
}
#define CP16(dst, src) \
    asm volatile("cp.async.cg.shared.global [%0], [%1], 16;" :: "r"(dst), "l"(src) : "memory")
#define CPCOMMIT() asm volatile("cp.async.commit_group;" ::: "memory")
#define CPWAIT(n)  asm volatile("cp.async.wait_group %0;" :: "n"(n) : "memory")

// m16n8k16 fp16 mma, fp32 accum
__device__ __forceinline__ void mma16(float* c, const uint32_t* a, uint32_t b0, uint32_t b1) {
    asm volatile(
        "mma.sync.aligned.m16n8k16.row.col.f32.f16.f16.f32 "
        "{%0,%1,%2,%3},{%4,%5,%6,%7},{%8,%9},{%0,%1,%2,%3};\n"
        : "+f"(c[0]), "+f"(c[1]), "+f"(c[2]), "+f"(c[3])
        : "r"(a[0]), "r"(a[1]), "r"(a[2]), "r"(a[3]), "r"(b0), "r"(b1));
}

// ldmatrix x4: four 8x8 b16 matrices; lane l supplies row address
__device__ __forceinline__ void ldsm4(uint32_t* r, uint32_t addr) {
    asm volatile("ldmatrix.sync.aligned.m8n8.x4.shared.b16 {%0,%1,%2,%3}, [%4];"
                 : "=r"(r[0]), "=r"(r[1]), "=r"(r[2]), "=r"(r[3]) : "r"(addr));
}

// ---------------------------------------------------------------------------
// Fused pre-convert: one launch.
// blocks [0, 2048): x fp32 -> fp16 elementwise (8 elems/thread)
// blocks [2048, 2048+4096): weight transpose [K][N] fp32 -> [N][K] fp16
//   sub-blocks: bx = idx & 127 over N-tiles (Wqkv 96 + Wproj 32), by = idx>>7
// ---------------------------------------------------------------------------
#define CVT_XBLK 2048
#define CVT_WBLK 4096

__global__ void cvt_fused_kernel(const float* __restrict__ x, __half* __restrict__ xh,
                                 const float* __restrict__ w1, __half* __restrict__ d1,
                                 const float* __restrict__ w2, __half* __restrict__ d2) {
    __shared__ float tile[32][33];
    const int bid = blockIdx.x;
    const int tid = threadIdx.x;
    if (bid < CVT_XBLK) {
        int i = (bid * 256 + tid) * 8;
        float4 v0 = *(const float4*)(x + i);
        float4 v1 = *(const float4*)(x + i + 4);
        uint4 u = { pack_h2(v0.x, v0.y), pack_h2(v0.z, v0.w),
                    pack_h2(v1.x, v1.y), pack_h2(v1.z, v1.w) };
        *(uint4*)(xh + i) = u;
        return;
    }
    const int idx = bid - CVT_XBLK;
    const int bx  = idx & 127;
    const int k0  = (idx >> 7) * 32;
    const float* src;
    __half* dst;
    int N, n0;
    if (bx < QKVN / 32) { src = w1; dst = d1; N = QKVN; n0 = bx * 32; }
    else                { src = w2; dst = d2; N = DIM;  n0 = (bx - QKVN / 32) * 32; }
    const int tx = tid & 31, ty = tid >> 5;
    for (int i = ty; i < 32; i += 8)
        tile[i][tx] = src[(size_t)(k0 + i) * N + n0 + tx];
    __syncthreads();
    for (int i = ty; i < 32; i += 8)
        dst[(size_t)(n0 + i) * DIM + k0 + tx] = __float2half_rn(tile[tx][i]);
}

// ---------------------------------------------------------------------------
// fp16 GEMM: tile 128x128, BK=64, 3 stages cp.async (CPWAIT(1)), 256 threads,
// 2 CTAs/SM, warp tile 32x64, ldmatrix at 144 B stride. (frozen — r12 best)
// ---------------------------------------------------------------------------
#define GA_ST 18432
#define GSTAGE (2 * GA_ST)             // A+B per stage: 36864
#define GSMEM (3 * GSTAGE)             // 110592 B -> 2 CTAs/SM

__device__ __forceinline__ void g_issue64(const __half* A, const __half* Bt,
                                          int m0, int n0, int t, int tid, uint32_t sb) {
    const uint32_t abase = sb + (t % 3) * GSTAGE;
    const uint32_t bbase = abase + GA_ST;
#pragma unroll
    for (int i = 0; i < 4; i++) {
        const int id = tid + i * 256;
        const int r = id >> 3, c = id & 7;
        CP16(abase + r * 144 + c * 16, A  + (size_t)(m0 + r) * 1024 + t * 64 + c * 8);
        CP16(bbase + r * 144 + c * 16, Bt + (size_t)(n0 + r) * 1024 + t * 64 + c * 8);
    }
    CPCOMMIT();
}

template<int MODE>
__global__ __launch_bounds__(256, 2)
void gemm_h(const __half* __restrict__ A, const __half* __restrict__ Bt,
            const float* __restrict__ bias, float* __restrict__ C, int N,
            __half* __restrict__ oq, __half* __restrict__ ok, __half* __restrict__ ovt)
{
    extern __shared__ uint32_t sw[];
    const uint32_t sb = smem_u32(sw);

    const int tid  = threadIdx.x;
    const int lane = tid & 31;
    const int wid  = tid >> 5;
    const int g    = lane >> 2;
    const int tg   = lane & 3;
    const int warp_m = (wid & 3) * 32;
    const int warp_n = (wid >> 2) * 64;
    const int m0 = blockIdx.y * 128;
    const int n0 = blockIdx.x * 128;

    const int lrow = (lane & 7) + ((lane >> 3) & 1) * 8;
    const int lcol = lane >> 4;
    const uint32_t aOff = (uint32_t)((warp_m + lrow) * 144 + lcol * 16);
    const uint32_t bOff = (uint32_t)((warp_n + lrow) * 144 + lcol * 16);

    float acc[2][8][4];
#pragma unroll
    for (int mt = 0; mt < 2; mt++)
#pragma unroll
        for (int nt = 0; nt < 8; nt++)
#pragma unroll
            for (int i = 0; i < 4; i++) acc[mt][nt][i] = 0.f;

    g_issue64(A, Bt, m0, n0, 0, tid, sb);
    g_issue64(A, Bt, m0, n0, 1, tid, sb);

    for (int t = 0; t < 16; ++t) {
        if (t < 15) { CPWAIT(1); } else { CPWAIT(0); }
        __syncthreads();
        if (t + 2 < 16) g_issue64(A, Bt, m0, n0, t + 2, tid, sb);

        const uint32_t aS = sb + (t % 3) * GSTAGE;
        const uint32_t bS = aS + GA_ST;

#pragma unroll
        for (int kt = 0; kt < 4; ++kt) {
            uint32_t afr[2][4];
            ldsm4(afr[0], aS + aOff + kt * 32);
            ldsm4(afr[1], aS + aOff + 2304 + kt * 32);
            uint32_t bfr[4][4];
#pragma unroll
            for (int ntp = 0; ntp < 4; ntp++)
                ldsm4(bfr[ntp], bS + bOff + ntp * 2304 + kt * 32);
#pragma unroll
            for (int mt = 0; mt < 2; mt++)
#pragma unroll
                for (int ntp = 0; ntp < 4; ntp++) {
                    mma16(acc[mt][2*ntp],   afr[mt], bfr[ntp][0], bfr[ntp][2]);
                    mma16(acc[mt][2*ntp+1], afr[mt], bfr[ntp][1], bfr[ntp][3]);
                }
        }
    }

    // epilogue
    const int rowB = m0 + warp_m;
    const int colB = n0 + warp_n;
#pragma unroll
    for (int mt = 0; mt < 2; mt++) {
#pragma unroll
        for (int nt = 0; nt < 8; nt++) {
            const int r = rowB + mt * 16 + g;
            const int c = colB + nt * 8 + 2 * tg;
            const float bv0 = bias[c], bv1 = bias[c + 1];
            const float v00 = acc[mt][nt][0] + bv0;
            const float v01 = acc[mt][nt][1] + bv1;
            const float v10 = acc[mt][nt][2] + bv0;
            const float v11 = acc[mt][nt][3] + bv1;
            if (MODE == 0) {
                const int sel = c >> 10;
                const int cc  = c & 1023;
                const int h   = cc >> 6;
                const int d   = cc & 63;
                const int b0_ = r >> 11,        t0_ = r & 2047;
                const int b1_ = (r + 8) >> 11,  t1_ = (r + 8) & 2047;
                if (sel < 2) {
                    __half* dst = (sel == 0) ? oq : ok;
                    const size_t i0 = (((size_t)(b0_ * NH + h) * SEQ) + t0_) * HD + d;
                    const size_t i1 = (((size_t)(b1_ * NH + h) * SEQ) + t1_) * HD + d;
                    *(uint32_t*)&dst[i0] = pack_h2(v00, v01);
                    *(uint32_t*)&dst[i1] = pack_h2(v10, v11);
                } else {
                    const size_t base0 = ((size_t)(b0_ * NH + h) * HD + d) * SEQ + t0_;
                    const size_t base1 = ((size_t)(b1_ * NH + h) * HD + d) * SEQ + t1_;
                    ovt[base0]       = __float2half_rn(v00);
                    ovt[base0 + SEQ] = __float2half_rn(v01);
                    ovt[base1]       = __float2half_rn(v10);
                    ovt[base1 + SEQ] = __float2half_rn(v11);
                }
            } else {
                *(float2*)&C[(size_t)r * N + c]       = make_float2(v00, v01);
                *(float2*)&C[(size_t)(r + 8) * N + c] = make_float2(v10, v11);
            }
        }
    }
}

// ---------------------------------------------------------------------------
// Flash attention, fp16 m16n8k16, Br=128 x Bc=64, 256 threads, 2 CTAs/SM.
// FA2 register-P; Q pre-scaled 0.125; 3-buffer KV ring (one sync/tile);
// exp2 softmax; tensor-core row sums; LAST-TILE SKIP: in tile kb=2qb+1 rows
// 0-63 are fully masked (col >= qb*128+64 > row), so warps 0-3 skip compute
// (provably no effect on m/l/O), freeing their SMSP issue slots.
// ---------------------------------------------------------------------------
#define KVBUF 9216                     // 64 rows * 144 B
#define AQ_BYTES 18432                 // Q region: 128 * 144
#define ASMEM (AQ_BYTES + 6 * KVBUF)   // 73728 B -> 2 CTAs/SM

__device__ __forceinline__ void issue_kv(const __half* k, const __half* vt,
                                         int bh, int kb, int buf, int tid,
                                         uint32_t kbase, uint32_t vbase) {
    const __half* ksrc = k  + ((size_t)bh * SEQ + (size_t)kb * 64) * HD;
    const __half* vsrc = vt + (size_t)bh * HD * SEQ + (size_t)kb * 64;
    const uint32_t kb_ = kbase + buf * KVBUF;
    const uint32_t vb_ = vbase + buf * KVBUF;
#pragma unroll
    for (int i = 0; i < 2; i++) {
        const int id = tid + i * 256;
        const int r = id >> 3, c = id & 7;
        CP16(kb_ + r * 144 + c * 16, ksrc + (size_t)r * HD + c * 8);
        CP16(vb_ + r * 144 + c * 16, vsrc + (size_t)r * SEQ + c * 8);
    }
    CPCOMMIT();
}

__global__ __launch_bounds__(256, 2)
void attn_h(const __half* __restrict__ q, const __half* __restrict__ k,
            const __half* __restrict__ vt, __half* __restrict__ out)
{
    extern __shared__ uint32_t sw[];
    const uint32_t sb    = smem_u32(sw);
    const uint32_t kbase = sb + AQ_BYTES;
    const uint32_t vbase = kbase + 3 * KVBUF;

    const int tid  = threadIdx.x;
    const int lane = tid & 31;
    const int wid  = tid >> 5;
    const int g    = lane >> 2;
    const int tg   = lane & 3;
    const int wbase = wid * 16;

    const int lrow = (lane & 7) + ((lane >> 3) & 1) * 8;
    const int lcol = lane >> 4;
    const uint32_t qpOff = (uint32_t)((wbase + lrow) * 144 + lcol * 16);
    const uint32_t kvOff = (uint32_t)(lrow * 144 + lcol * 16);

    const int bh = blockIdx.y;
    const int qb = (gridDim.x - 1) - blockIdx.x;   // big tiles first
    const int b_ = bh >> 4;
    const int h  = bh & 15;
    const int nkv = 2 * qb + 2;
    const uint32_t ONES2 = 0x3C003C00u;            // (1.0h, 1.0h)

    // prologue: G0 = Q + KV0 (buf 0), G1 = KV1 (buf 1)
    {
        const __half* qsrc = q + ((size_t)bh * SEQ + (size_t)qb * 128) * HD;
#pragma unroll
        for (int i = 0; i < 4; i++) {
            const int id = tid + i * 256;
            const int r = id >> 3, c = id & 7;
            CP16(sb + r * 144 + c * 16, qsrc + (size_t)r * HD + c * 8);
        }
        const __half* ksrc = k  + (size_t)bh * SEQ * HD;
        const __half* vsrc = vt + (size_t)bh * HD * SEQ;
#pragma unroll
        for (int i = 0; i < 2; i++) {
            const int id = tid + i * 256;
            const int r = id >> 3, c = id & 7;
            CP16(kbase + r * 144 + c * 16, ksrc + (size_t)r * HD + c * 8);
            CP16(vbase + r * 144 + c * 16, vsrc + (size_t)r * SEQ + c * 8);
        }
        CPCOMMIT();
        issue_kv(k, vt, bh, 1, 1, tid, kbase, vbase);
    }
    CPWAIT(1);
    __syncthreads();

    // Q fragments in registers, pre-scaled by 1/sqrt(64)=0.125 (exact in fp16)
    uint32_t qf[4][4];
    {
        const __half2 sc = __half2half2(__float2half_rn(0.125f));
#pragma unroll
        for (int kt = 0; kt < 4; kt++) {
            ldsm4(qf[kt], sb + qpOff + kt * 32);
#pragma unroll
            for (int i = 0; i < 4; i++) {
                __half2 v = *reinterpret_cast<__half2*>(&qf[kt][i]);
                v = __hmul2(v, sc);
                qf[kt][i] = *reinterpret_cast<uint32_t*>(&v);
            }
        }
    }

    const float L2E = 1.4426950408889634f;
    float m0 = -INFINITY, m1 = -INFINITY;     // raw-domain running max
    float m0_2 = -INFINITY, m1_2 = -INFINITY; // log2-domain (m * L2E)
    float l0 = 0.f, l1 = 0.f;
    float O[8][4];
#pragma unroll
    for (int nt = 0; nt < 8; nt++)
#pragma unroll
        for (int i = 0; i < 4; i++) O[nt][i] = 0.f;

    for (int kb = 0; kb < nkv; ++kb) {
        if (kb > 0) {
            if (kb + 1 < nkv) { CPWAIT(1); } else { CPWAIT(0); }
            __syncthreads();   // also fences reads of tile kb-1's buffers
        }
        if (kb + 2 < nkv) issue_kv(k, vt, bh, kb + 2, (kb + 2) % 3, tid, kbase, vbase);

        // Last diagonal tile: rows 0-63 fully masked (P==0, m/l/O unchanged).
        // Warps 0-3 skip all compute; no barriers inside the tile body.
        if (kb == 2 * qb + 1 && wid < 4) continue;

        const uint32_t kB = kbase + (kb % 3) * KVBUF;
        const uint32_t vB = vbase + (kb % 3) * KVBUF;

        // S = (Q/8) @ K^T
        float s_[8][4];
#pragma unroll
        for (int nt = 0; nt < 8; nt++)
#pragma unroll
            for (int i = 0; i < 4; i++) s_[nt][i] = 0.f;
#pragma unroll
        for (int kt = 0; kt < 4; kt++) {
            uint32_t bfr[4][4];
#pragma unroll
            for (int ntp = 0; ntp < 4; ntp++)
                ldsm4(bfr[ntp], kB + kvOff + ntp * 2304 + kt * 32);
#pragma unroll
            for (int ntp = 0; ntp < 4; ntp++) {
                mma16(s_[2*ntp],   qf[kt], bfr[ntp][0], bfr[ntp][2]);
                mma16(s_[2*ntp+1], qf[kt], bfr[ntp][1], bfr[ntp][3]);
            }
        }

        // causal mask (only in the last two kv tiles)
        if (kb >= 2 * qb) {
            const int rg0 = qb * 128 + wbase + g;
#pragma unroll
            for (int nt = 0; nt < 8; nt++) {
                const int cg = kb * 64 + nt * 8 + 2 * tg;
                if (cg > rg0)         s_[nt][0] = -INFINITY;
                if (cg + 1 > rg0)     s_[nt][1] = -INFINITY;
                if (cg > rg0 + 8)     s_[nt][2] = -INFINITY;
                if (cg + 1 > rg0 + 8) s_[nt][3] = -INFINITY;
            }
        }

        // online softmax (log2 domain); row max via quad shuffle
        float mx0 = -INFINITY, mx1 = -INFINITY;
#pragma unroll
        for (int nt = 0; nt < 8; nt++) {
            mx0 = fmaxf(mx0, fmaxf(s_[nt][0], s_[nt][1]));
            mx1 = fmaxf(mx1, fmaxf(s_[nt][2], s_[nt][3]));
        }
#pragma unroll
        for (int off = 1; off < 4; off <<= 1) {
            mx0 = fmaxf(mx0, __shfl_xor_sync(0xffffffffu, mx0, off));
            mx1 = fmaxf(mx1, __shfl_xor_sync(0xffffffffu, mx1, off));
        }
        const float mn0 = fmaxf(m0, mx0);
        const float mn1 = fmaxf(m1, mx1);
        const float mn0_2 = mn0 * L2E;
        const float mn1_2 = mn1 * L2E;
        const float al0 = exp2f(m0_2 - mn0_2);
        const float al1 = exp2f(m1_2 - mn1_2);
        m0 = mn0; m1 = mn1; m0_2 = mn0_2; m1_2 = mn1_2;
        const float nm0 = -mn0_2, nm1 = -mn1_2;

        // exponentiate (row sum comes from the MMA below)
#pragma unroll
        for (int nt = 0; nt < 8; nt++) {
            s_[nt][0] = exp2f(fmaf(s_[nt][0], L2E, nm0));
            s_[nt][1] = exp2f(fmaf(s_[nt][1], L2E, nm0));
            s_[nt][2] = exp2f(fmaf(s_[nt][2], L2E, nm1));
            s_[nt][3] = exp2f(fmaf(s_[nt][3], L2E, nm1));
        }
#pragma unroll
        for (int nt = 0; nt < 8; nt++) {
            O[nt][0] *= al0; O[nt][1] *= al0;
            O[nt][2] *= al1; O[nt][3] *= al1;
        }

        // P stays in registers; O += P @ V and lsum += P @ ones (tensor core)
        float lsum[4] = {0.f, 0.f, 0.f, 0.f};
#pragma unroll
        for (int kt = 0; kt < 4; kt++) {
            uint32_t pa[4];
            pa[0] = pack_h2(s_[2*kt][0],   s_[2*kt][1]);
            pa[1] = pack_h2(s_[2*kt][2],   s_[2*kt][3]);
            pa[2] = pack_h2(s_[2*kt+1][0], s_[2*kt+1][1]);
            pa[3] = pack_h2(s_[2*kt+1][2], s_[2*kt+1][3]);
            uint32_t bfr[4][4];
#pragma unroll
            for (int ntp = 0; ntp < 4; ntp++)
                ldsm4(bfr[ntp], vB + kvOff + ntp * 2304 + kt * 32);
#pragma unroll
            for (int ntp = 0; ntp < 4; ntp++) {
                mma16(O[2*ntp],   pa, bfr[ntp][0], bfr[ntp][2]);
                mma16(O[2*ntp+1], pa, bfr[ntp][1], bfr[ntp][3]);
            }
            mma16(lsum, pa, ONES2, ONES2);   // row sums (quad-wide via k-reduce)
        }
        l0 = l0 * al0 + lsum[0];
        l1 = l1 * al1 + lsum[2];
        // no bottom sync: 3-buffer ring defers the reuse guard to next top sync
    }

    // normalize, write fp16 to g_attn [B*T, C]
    const float inv0 = 1.f / l0;
    const float inv1 = 1.f / l1;
    const int t0 = qb * 128 + wbase + g;
#pragma unroll
    for (int nt = 0; nt < 8; nt++) {
        const int c = h * HD + nt * 8 + 2 * tg;
        *(uint32_t*)&out[((size_t)(b_ * SEQ + t0)) * DIM + c] =
            pack_h2(O[nt][0] * inv0, O[nt][1] * inv0);
        *(uint32_t*)&out[((size_t)(b_ * SEQ + t0 + 8)) * DIM + c] =
            pack_h2(O[nt][2] * inv1, O[nt][3] * inv1);
    }
}

// ---------------------------------------------------------------------------
extern "C" void kernel_launch(void* const* d_in, const int* in_sizes, int n_in,
                              void* d_out, int out_size)
{
    const float* x     = (const float*)d_in[0];
    const float* Wqkv  = (const float*)d_in[1];
    const float* bqkv  = (const float*)d_in[2];
    const float* Wproj = (const float*)d_in[3];
    const float* bproj = (const float*)d_in[4];
    float* out = (float*)d_out;

    __half *gq, *gk, *gvt, *gattn, *gxh, *gwqkvh, *gwprojh;
    cudaGetSymbolAddress((void**)&gq, g_q);
    cudaGetSymbolAddress((void**)&gk, g_k);
    cudaGetSymbolAddress((void**)&gvt, g_vt);
    cudaGetSymbolAddress((void**)&gattn, g_attn);
    cudaGetSymbolAddress((void**)&gxh, g_xh);
    cudaGetSymbolAddress((void**)&gwqkvh, g_wqkvh);
    cudaGetSymbolAddress((void**)&gwprojh, g_wprojh);

    cudaFuncSetAttribute(gemm_h<0>, cudaFuncAttributeMaxDynamicSharedMemorySize, GSMEM);
    cudaFuncSetAttribute(gemm_h<1>, cudaFuncAttributeMaxDynamicSharedMemorySize, GSMEM);
    cudaFuncSetAttribute(attn_h,   cudaFuncAttributeMaxDynamicSharedMemorySize, ASMEM);

    // 0) fused fp16 pre-convert (x + both weight transposes, one launch)
    cvt_fused_kernel<<<CVT_XBLK + CVT_WBLK, 256>>>(x, gxh, Wqkv, gwqkvh, Wproj, gwprojh);

    // 1) QKV projection + head scatter (V transposed)
    {
        dim3 grid(QKVN / 128, BT / 128);   // (24, 32)
        gemm_h<0><<<grid, 256, GSMEM>>>(gxh, gwqkvh, bqkv, nullptr,
                                        QKVN, gq, gk, gvt);
    }
    // 2) Causal flash attention
    {
        dim3 grid(SEQ / 128, BATCH * NH);  // (16, 32)
        attn_h<<<grid, 256, ASMEM>>>(gq, gk, gvt, gattn);
    }
    // 3) Output projection
    {
        dim3 grid(DIM / 128, BT / 128);    // (8, 32)
        gemm_h<1><<<grid, 256, GSMEM>>>(gattn, gwprojh, bproj, out,
                                        DIM, nullptr, nullptr, nullptr);
    }
    (void)in_sizes; (void)n_in; (void)out_size;
}

// round 16
// speedup vs baseline: 1.0455x; 1.0122x over previous
#include <cuda_runtime.h>
#include <cuda_fp16.h>
#include <math.h>
#include <stdint.h>

#define BATCH 2
#define SEQ   2048
#define DIM   1024
#define NH    16
#define HD    64
#define BT    (BATCH*SEQ)      // 4096
#define QKVN  (3*DIM)          // 3072

// Scratch (static device arrays; no allocations allowed)
__device__ __half g_q[BATCH*NH*SEQ*HD];     // [B,H,T,D]
__device__ __half g_k[BATCH*NH*SEQ*HD];     // [B,H,T,D]
__device__ __half g_vt[BATCH*NH*HD*SEQ];    // [B,H,D,T]  (transposed V)
__device__ __half g_attn[BT*DIM];           // [B*T, C]
__device__ __half g_xh[BT*DIM];             // fp16(x)
__device__ __half g_wqkvh[QKVN*DIM];        // fp16(W_qkv^T)  [N][K]
__device__ __half g_wprojh[DIM*DIM];        // fp16(W_proj^T) [N][K]

// ---------------------------------------------------------------------------
__device__ __forceinline__ uint32_t smem_u32(const void* p) {
    uint32_t a;
    asm("{ .reg .u64 t; cvta.to.shared.u64 t, %1; cvt.u32.u64 %0, t; }" : "=r"(a) : "l"(p));
    return a;
}
__device__ __forceinline__ uint32_t pack_h2(float lo, float hi) {
    __half2 h = __floats2half2_rn(lo, hi);
    return *reinterpret_cast<uint32_t*>(&h);
}
#define CP16(dst, src) \
    asm volatile("cp.async.cg.shared.global [%0], [%1], 16;" :: "r"(dst), "l"(src) : "memory")
#define CPCOMMIT() asm volatile("cp.async.commit_group;" ::: "memory")
#define CPWAIT(n)  asm volatile("cp.async.wait_group %0;" :: "n"(n) : "memory")

// m16n8k16 fp16 mma, fp32 accum
__device__ __forceinline__ void mma16(float* c, const uint32_t* a, uint32_t b0, uint32_t b1) {
    asm volatile(
        "mma.sync.aligned.m16n8k16.row.col.f32.f16.f16.f32 "
        "{%0,%1,%2,%3},{%4,%5,%6,%7},{%8,%9},{%0,%1,%2,%3};\n"
        : "+f"(c[0]), "+f"(c[1]), "+f"(c[2]), "+f"(c[3])
        : "r"(a[0]), "r"(a[1]), "r"(a[2]), "r"(a[3]), "r"(b0), "r"(b1));
}

// ldmatrix x4: four 8x8 b16 matrices; lane l supplies row address
__device__ __forceinline__ void ldsm4(uint32_t* r, uint32_t addr) {
    asm volatile("ldmatrix.sync.aligned.m8n8.x4.shared.b16 {%0,%1,%2,%3}, [%4];"
                 : "=r"(r[0]), "=r"(r[1]), "=r"(r[2]), "=r"(r[3]) : "r"(addr));
}

// ---------------------------------------------------------------------------
// Fused pre-convert: one launch.
// blocks [0, 2048): x fp32 -> fp16 elementwise (8 elems/thread)
// blocks [2048, 2048+4096): weight transpose [K][N] fp32 -> [N][K] fp16
// ---------------------------------------------------------------------------
#define CVT_XBLK 2048
#define CVT_WBLK 4096

__global__ void cvt_fused_kernel(const float* __restrict__ x, __half* __restrict__ xh,
                                 const float* __restrict__ w1, __half* __restrict__ d1,
                                 const float* __restrict__ w2, __half* __restrict__ d2) {
    __shared__ float tile[32][33];
    const int bid = blockIdx.x;
    const int tid = threadIdx.x;
    if (bid < CVT_XBLK) {
        int i = (bid * 256 + tid) * 8;
        float4 v0 = *(const float4*)(x + i);
        float4 v1 = *(const float4*)(x + i + 4);
        uint4 u = { pack_h2(v0.x, v0.y), pack_h2(v0.z, v0.w),
                    pack_h2(v1.x, v1.y), pack_h2(v1.z, v1.w) };
        *(uint4*)(xh + i) = u;
        return;
    }
    const int idx = bid - CVT_XBLK;
    const int bx  = idx & 127;
    const int k0  = (idx >> 7) * 32;
    const float* src;
    __half* dst;
    int N, n0;
    if (bx < QKVN / 32) { src = w1; dst = d1; N = QKVN; n0 = bx * 32; }
    else                { src = w2; dst = d2; N = DIM;  n0 = (bx - QKVN / 32) * 32; }
    const int tx = tid & 31, ty = tid >> 5;
    for (int i = ty; i < 32; i += 8)
        tile[i][tx] = src[(size_t)(k0 + i) * N + n0 + tx];
    __syncthreads();
    for (int i = ty; i < 32; i += 8)
        dst[(size_t)(n0 + i) * DIM + k0 + tx] = __float2half_rn(tile[tx][i]);
}

// ---------------------------------------------------------------------------
// fp16 GEMM: tile 128x128, BK=64, 3 stages cp.async (CPWAIT(1)), 256 threads,
// 2 CTAs/SM, warp tile 32x64, ldmatrix at 144 B stride. (frozen — plateau)
// ---------------------------------------------------------------------------
#define GA_ST 18432
#define GSTAGE (2 * GA_ST)             // A+B per stage: 36864
#define GSMEM (3 * GSTAGE)             // 110592 B -> 2 CTAs/SM

__device__ __forceinline__ void g_issue64(const __half* A, const __half* Bt,
                                          int m0, int n0, int t, int tid, uint32_t sb) {
    const uint32_t abase = sb + (t % 3) * GSTAGE;
    const uint32_t bbase = abase + GA_ST;
#pragma unroll
    for (int i = 0; i < 4; i++) {
        const int id = tid + i * 256;
        const int r = id >> 3, c = id & 7;
        CP16(abase + r * 144 + c * 16, A  + (size_t)(m0 + r) * 1024 + t * 64 + c * 8);
        CP16(bbase + r * 144 + c * 16, Bt + (size_t)(n0 + r) * 1024 + t * 64 + c * 8);
    }
    CPCOMMIT();
}

template<int MODE>
__global__ __launch_bounds__(256, 2)
void gemm_h(const __half* __restrict__ A, const __half* __restrict__ Bt,
            const float* __restrict__ bias, float* __restrict__ C, int N,
            __half* __restrict__ oq, __half* __restrict__ ok, __half* __restrict__ ovt)
{
    extern __shared__ uint32_t sw[];
    const uint32_t sb = smem_u32(sw);

    const int tid  = threadIdx.x;
    const int lane = tid & 31;
    const int wid  = tid >> 5;
    const int g    = lane >> 2;
    const int tg   = lane & 3;
    const int warp_m = (wid & 3) * 32;
    const int warp_n = (wid >> 2) * 64;
    const int m0 = blockIdx.y * 128;
    const int n0 = blockIdx.x * 128;

    const int lrow = (lane & 7) + ((lane >> 3) & 1) * 8;
    const int lcol = lane >> 4;
    const uint32_t aOff = (uint32_t)((warp_m + lrow) * 144 + lcol * 16);
    const uint32_t bOff = (uint32_t)((warp_n + lrow) * 144 + lcol * 16);

    float acc[2][8][4];
#pragma unroll
    for (int mt = 0; mt < 2; mt++)
#pragma unroll
        for (int nt = 0; nt < 8; nt++)
#pragma unroll
            for (int i = 0; i < 4; i++) acc[mt][nt][i] = 0.f;

    g_issue64(A, Bt, m0, n0, 0, tid, sb);
    g_issue64(A, Bt, m0, n0, 1, tid, sb);

    for (int t = 0; t < 16; ++t) {
        if (t < 15) { CPWAIT(1); } else { CPWAIT(0); }
        __syncthreads();
        if (t + 2 < 16) g_issue64(A, Bt, m0, n0, t + 2, tid, sb);

        const uint32_t aS = sb + (t % 3) * GSTAGE;
        const uint32_t bS = aS + GA_ST;

#pragma unroll
        for (int kt = 0; kt < 4; ++kt) {
            uint32_t afr[2][4];
            ldsm4(afr[0], aS + aOff + kt * 32);
            ldsm4(afr[1], aS + aOff + 2304 + kt * 32);
            uint32_t bfr[4][4];
#pragma unroll
            for (int ntp = 0; ntp < 4; ntp++)
                ldsm4(bfr[ntp], bS + bOff + ntp * 2304 + kt * 32);
#pragma unroll
            for (int mt = 0; mt < 2; mt++)
#pragma unroll
                for (int ntp = 0; ntp < 4; ntp++) {
                    mma16(acc[mt][2*ntp],   afr[mt], bfr[ntp][0], bfr[ntp][2]);
                    mma16(acc[mt][2*ntp+1], afr[mt], bfr[ntp][1], bfr[ntp][3]);
                }
        }
    }

    // epilogue
    const int rowB = m0 + warp_m;
    const int colB = n0 + warp_n;
#pragma unroll
    for (int mt = 0; mt < 2; mt++) {
#pragma unroll
        for (int nt = 0; nt < 8; nt++) {
            const int r = rowB + mt * 16 + g;
            const int c = colB + nt * 8 + 2 * tg;
            const float bv0 = bias[c], bv1 = bias[c + 1];
            const float v00 = acc[mt][nt][0] + bv0;
            const float v01 = acc[mt][nt][1] + bv1;
            const float v10 = acc[mt][nt][2] + bv0;
            const float v11 = acc[mt][nt][3] + bv1;
            if (MODE == 0) {
                const int sel = c >> 10;
                const int cc  = c & 1023;
                const int h   = cc >> 6;
                const int d   = cc & 63;
                const int b0_ = r >> 11,        t0_ = r & 2047;
                const int b1_ = (r + 8) >> 11,  t1_ = (r + 8) & 2047;
                if (sel < 2) {
                    __half* dst = (sel == 0) ? oq : ok;
                    const size_t i0 = (((size_t)(b0_ * NH + h) * SEQ) + t0_) * HD + d;
                    const size_t i1 = (((size_t)(b1_ * NH + h) * SEQ) + t1_) * HD + d;
                    *(uint32_t*)&dst[i0] = pack_h2(v00, v01);
                    *(uint32_t*)&dst[i1] = pack_h2(v10, v11);
                } else {
                    const size_t base0 = ((size_t)(b0_ * NH + h) * HD + d) * SEQ + t0_;
                    const size_t base1 = ((size_t)(b1_ * NH + h) * HD + d) * SEQ + t1_;
                    ovt[base0]       = __float2half_rn(v00);
                    ovt[base0 + SEQ] = __float2half_rn(v01);
                    ovt[base1]       = __float2half_rn(v10);
                    ovt[base1 + SEQ] = __float2half_rn(v11);
                }
            } else {
                *(float2*)&C[(size_t)r * N + c]       = make_float2(v00, v01);
                *(float2*)&C[(size_t)(r + 8) * N + c] = make_float2(v10, v11);
            }
        }
    }
}

// ---------------------------------------------------------------------------
// Flash attention, fp16 m16n8k16, Br=128 x Bc=64, 256 threads, 2 CTAs/SM.
// FA2 register-P; Q pre-scaled 0.125; 3-buffer KV ring (one sync/tile);
// exp2 softmax; tensor-core row sums; last-tile skip for warps 0-3; mask
// arithmetic only where it can trigger: (wid<4) == (kb==2qb).
// ---------------------------------------------------------------------------
#define KVBUF 9216                     // 64 rows * 144 B
#define AQ_BYTES 18432                 // Q region: 128 * 144
#define ASMEM (AQ_BYTES + 6 * KVBUF)   // 73728 B -> 2 CTAs/SM

__device__ __forceinline__ void issue_kv(const __half* k, const __half* vt,
                                         int bh, int kb, int buf, int tid,
                                         uint32_t kbase, uint32_t vbase) {
    const __half* ksrc = k  + ((size_t)bh * SEQ + (size_t)kb * 64) * HD;
    const __half* vsrc = vt + (size_t)bh * HD * SEQ + (size_t)kb * 64;
    const uint32_t kb_ = kbase + buf * KVBUF;
    const uint32_t vb_ = vbase + buf * KVBUF;
#pragma unroll
    for (int i = 0; i < 2; i++) {
        const int id = tid + i * 256;
        const int r = id >> 3, c = id & 7;
        CP16(kb_ + r * 144 + c * 16, ksrc + (size_t)r * HD + c * 8);
        CP16(vb_ + r * 144 + c * 16, vsrc + (size_t)r * SEQ + c * 8);
    }
    CPCOMMIT();
}

__global__ __launch_bounds__(256, 2)
void attn_h(const __half* __restrict__ q, const __half* __restrict__ k,
            const __half* __restrict__ vt, __half* __restrict__ out)
{
    extern __shared__ uint32_t sw[];
    const uint32_t sb    = smem_u32(sw);
    const uint32_t kbase = sb + AQ_BYTES;
    const uint32_t vbase = kbase + 3 * KVBUF;

    const int tid  = threadIdx.x;
    const int lane = tid & 31;
    const int wid  = tid >> 5;
    const int g    = lane >> 2;
    const int tg   = lane & 3;
    const int wbase = wid * 16;

    const int lrow = (lane & 7) + ((lane >> 3) & 1) * 8;
    const int lcol = lane >> 4;
    const uint32_t qpOff = (uint32_t)((wbase + lrow) * 144 + lcol * 16);
    const uint32_t kvOff = (uint32_t)(lrow * 144 + lcol * 16);

    const int bh = blockIdx.y;
    const int qb = (gridDim.x - 1) - blockIdx.x;   // big tiles first
    const int b_ = bh >> 4;
    const int h  = bh & 15;
    const int diag0 = 2 * qb;                      // first diagonal tile idx
    const int nkv = diag0 + 2;
    const uint32_t ONES2 = 0x3C003C00u;            // (1.0h, 1.0h)

    // prologue: G0 = Q + KV0 (buf 0), G1 = KV1 (buf 1)
    {
        const __half* qsrc = q + ((size_t)bh * SEQ + (size_t)qb * 128) * HD;
#pragma unroll
        for (int i = 0; i < 4; i++) {
            const int id = tid + i * 256;
            const int r = id >> 3, c = id & 7;
            CP16(sb + r * 144 + c * 16, qsrc + (size_t)r * HD + c * 8);
        }
        const __half* ksrc = k  + (size_t)bh * SEQ * HD;
        const __half* vsrc = vt + (size_t)bh * HD * SEQ;
#pragma unroll
        for (int i = 0; i < 2; i++) {
            const int id = tid + i * 256;
            const int r = id >> 3, c = id & 7;
            CP16(kbase + r * 144 + c * 16, ksrc + (size_t)r * HD + c * 8);
            CP16(vbase + r * 144 + c * 16, vsrc + (size_t)r * SEQ + c * 8);
        }
        CPCOMMIT();
        issue_kv(k, vt, bh, 1, 1, tid, kbase, vbase);
    }
    CPWAIT(1);
    __syncthreads();

    // Q fragments in registers, pre-scaled by 1/sqrt(64)=0.125 (exact in fp16)
    uint32_t qf[4][4];
    {
        const __half2 sc = __half2half2(__float2half_rn(0.125f));
#pragma unroll
        for (int kt = 0; kt < 4; kt++) {
            ldsm4(qf[kt], sb + qpOff + kt * 32);
#pragma unroll
            for (int i = 0; i < 4; i++) {
                __half2 v = *reinterpret_cast<__half2*>(&qf[kt][i]);
                v = __hmul2(v, sc);
                qf[kt][i] = *reinterpret_cast<uint32_t*>(&v);
            }
        }
    }

    const float L2E = 1.4426950408889634f;
    float m0 = -INFINITY, m1 = -INFINITY;     // raw-domain running max
    float m0_2 = -INFINITY, m1_2 = -INFINITY; // log2-domain (m * L2E)
    float l0 = 0.f, l1 = 0.f;
    float O[8][4];
#pragma unroll
    for (int nt = 0; nt < 8; nt++)
#pragma unroll
        for (int i = 0; i < 4; i++) O[nt][i] = 0.f;

    for (int kb = 0; kb < nkv; ++kb) {
        if (kb > 0) {
            if (kb + 1 < nkv) { CPWAIT(1); } else { CPWAIT(0); }
            __syncthreads();   // also fences reads of tile kb-1's buffers
        }
        if (kb + 2 < nkv) issue_kv(k, vt, bh, kb + 2, (kb + 2) % 3, tid, kbase, vbase);

        // Last diagonal tile: rows 0-63 fully masked (P==0, m/l/O unchanged).
        if (kb == diag0 + 1 && wid < 4) continue;

        const uint32_t kB = kbase + (kb % 3) * KVBUF;
        const uint32_t vB = vbase + (kb % 3) * KVBUF;

        // S = (Q/8) @ K^T
        float s_[8][4];
#pragma unroll
        for (int nt = 0; nt < 8; nt++)
#pragma unroll
            for (int i = 0; i < 4; i++) s_[nt][i] = 0.f;
#pragma unroll
        for (int kt = 0; kt < 4; kt++) {
            uint32_t bfr[4][4];
#pragma unroll
            for (int ntp = 0; ntp < 4; ntp++)
                ldsm4(bfr[ntp], kB + kvOff + ntp * 2304 + kt * 32);
#pragma unroll
            for (int ntp = 0; ntp < 4; ntp++) {
                mma16(s_[2*ntp],   qf[kt], bfr[ntp][0], bfr[ntp][2]);
                mma16(s_[2*ntp+1], qf[kt], bfr[ntp][1], bfr[ntp][3]);
            }
        }

        // causal mask — only where it can trigger:
        //   kb==diag0   -> only warps 0-3 cross the diagonal
        //   kb==diag0+1 -> only warps 4-7 (0-3 already skipped)
        if (kb >= diag0 && ((wid < 4) == (kb == diag0))) {
            const int rg0 = qb * 128 + wbase + g;
#pragma unroll
            for (int nt = 0; nt < 8; nt++) {
                const int cg = kb * 64 + nt * 8 + 2 * tg;
                if (cg > rg0)         s_[nt][0] = -INFINITY;
                if (cg + 1 > rg0)     s_[nt][1] = -INFINITY;
                if (cg > rg0 + 8)     s_[nt][2] = -INFINITY;
                if (cg + 1 > rg0 + 8) s_[nt][3] = -INFINITY;
            }
        }

        // online softmax (log2 domain); row max via quad shuffle
        float mx0 = -INFINITY, mx1 = -INFINITY;
#pragma unroll
        for (int nt = 0; nt < 8; nt++) {
            mx0 = fmaxf(mx0, fmaxf(s_[nt][0], s_[nt][1]));
            mx1 = fmaxf(mx1, fmaxf(s_[nt][2], s_[nt][3]));
        }
#pragma unroll
        for (int off = 1; off < 4; off <<= 1) {
            mx0 = fmaxf(mx0, __shfl_xor_sync(0xffffffffu, mx0, off));
            mx1 = fmaxf(mx1, __shfl_xor_sync(0xffffffffu, mx1, off));
        }
        const float mn0 = fmaxf(m0, mx0);
        const float mn1 = fmaxf(m1, mx1);
        const float mn0_2 = mn0 * L2E;
        const float mn1_2 = mn1 * L2E;
        const float al0 = exp2f(m0_2 - mn0_2);
        const float al1 = exp2f(m1_2 - mn1_2);
        m0 = mn0; m1 = mn1; m0_2 = mn0_2; m1_2 = mn1_2;
        const float nm0 = -mn0_2, nm1 = -mn1_2;

        // exponentiate (row sum comes from the MMA below)
#pragma unroll
        for (int nt = 0; nt < 8; nt++) {
            s_[nt][0] = exp2f(fmaf(s_[nt][0], L2E, nm0));
            s_[nt][1] = exp2f(fmaf(s_[nt][1], L2E, nm0));
            s_[nt][2] = exp2f(fmaf(s_[nt][2], L2E, nm1));
            s_[nt][3] = exp2f(fmaf(s_[nt][3], L2E, nm1));
        }
#pragma unroll
        for (int nt = 0; nt < 8; nt++) {
            O[nt][0] *= al0; O[nt][1] *= al0;
            O[nt][2] *= al1; O[nt][3] *= al1;
        }

        // P stays in registers; O += P @ V and lsum += P @ ones (tensor core)
        float lsum[4] = {0.f, 0.f, 0.f, 0.f};
#pragma unroll
        for (int kt = 0; kt < 4; kt++) {
            uint32_t pa[4];
            pa[0] = pack_h2(s_[2*kt][0],   s_[2*kt][1]);
            pa[1] = pack_h2(s_[2*kt][2],   s_[2*kt][3]);
            pa[2] = pack_h2(s_[2*kt+1][0], s_[2*kt+1][1]);
            pa[3] = pack_h2(s_[2*kt+1][2], s_[2*kt+1][3]);
            uint32_t bfr[4][4];
#pragma unroll
            for (int ntp = 0; ntp < 4; ntp++)
                ldsm4(bfr[ntp], vB + kvOff + ntp * 2304 + kt * 32);
#pragma unroll
            for (int ntp = 0; ntp < 4; ntp++) {
                mma16(O[2*ntp],   pa, bfr[ntp][0], bfr[ntp][2]);
                mma16(O[2*ntp+1], pa, bfr[ntp][1], bfr[ntp][3]);
            }
            mma16(lsum, pa, ONES2, ONES2);   // row sums (quad-wide via k-reduce)
        }
        l0 = l0 * al0 + lsum[0];
        l1 = l1 * al1 + lsum[2];
        // no bottom sync: 3-buffer ring defers the reuse guard to next top sync
    }

    // normalize, write fp16 to g_attn [B*T, C]
    const float inv0 = 1.f / l0;
    const float inv1 = 1.f / l1;
    const int t0 = qb * 128 + wbase + g;
#pragma unroll
    for (int nt = 0; nt < 8; nt++) {
        const int c = h * HD + nt * 8 + 2 * tg;
        *(uint32_t*)&out[((size_t)(b_ * SEQ + t0)) * DIM + c] =
            pack_h2(O[nt][0] * inv0, O[nt][1] * inv0);
        *(uint32_t*)&out[((size_t)(b_ * SEQ + t0 + 8)) * DIM + c] =
            pack_h2(O[nt][2] * inv1, O[nt][3] * inv1);
    }
}

// ---------------------------------------------------------------------------
extern "C" void kernel_launch(void* const* d_in, const int* in_sizes, int n_in,
                              void* d_out, int out_size)
{
    const float* x     = (const float*)d_in[0];
    const float* Wqkv  = (const float*)d_in[1];
    const float* bqkv  = (const float*)d_in[2];
    const float* Wproj = (const float*)d_in[3];
    const float* bproj = (const float*)d_in[4];
    float* out = (float*)d_out;

    __half *gq, *gk, *gvt, *gattn, *gxh, *gwqkvh, *gwprojh;
    cudaGetSymbolAddress((void**)&gq, g_q);
    cudaGetSymbolAddress((void**)&gk, g_k);
    cudaGetSymbolAddress((void**)&gvt, g_vt);
    cudaGetSymbolAddress((void**)&gattn, g_attn);
    cudaGetSymbolAddress((void**)&gxh, g_xh);
    cudaGetSymbolAddress((void**)&gwqkvh, g_wqkvh);
    cudaGetSymbolAddress((void**)&gwprojh, g_wprojh);

    cudaFuncSetAttribute(gemm_h<0>, cudaFuncAttributeMaxDynamicSharedMemorySize, GSMEM);
    cudaFuncSetAttribute(gemm_h<1>, cudaFuncAttributeMaxDynamicSharedMemorySize, GSMEM);
    cudaFuncSetAttribute(attn_h,   cudaFuncAttributeMaxDynamicSharedMemorySize, ASMEM);

    // 0) fused fp16 pre-convert (x + both weight transposes, one launch)
    cvt_fused_kernel<<<CVT_XBLK + CVT_WBLK, 256>>>(x, gxh, Wqkv, gwqkvh, Wproj, gwprojh);

    // 1) QKV projection + head scatter (V transposed)
    {
        dim3 grid(QKVN / 128, BT / 128);   // (24, 32)
        gemm_h<0><<<grid, 256, GSMEM>>>(gxh, gwqkvh, bqkv, nullptr,
                                        QKVN, gq, gk, gvt);
    }
    // 2) Causal flash attention
    {
        dim3 grid(SEQ / 128, BATCH * NH);  // (16, 32)
        attn_h<<<grid, 256, ASMEM>>>(gq, gk, gvt, gattn);
    }
    // 3) Output projection
    {
        dim3 grid(DIM / 128, BT / 128);    // (8, 32)
        gemm_h<1><<<grid, 256, GSMEM>>>(gattn, gwprojh, bproj, out,
                                        DIM, nullptr, nullptr, nullptr);
    }
    (void)in_sizes; (void)n_in; (void)out_size;
}

// round 17
// speedup vs baseline: 1.0470x; 1.0015x over previous
#include <cuda_runtime.h>
#include <cuda_fp16.h>
#include <math.h>
#include <stdint.h>

#define BATCH 2
#define SEQ   2048
#define DIM   1024
#define NH    16
#define HD    64
#define BT    (BATCH*SEQ)      // 4096
#define QKVN  (3*DIM)          // 3072

// Scratch (static device arrays; no allocations allowed)
__device__ __half g_q[BATCH*NH*SEQ*HD];     // [B,H,T,D]
__device__ __half g_k[BATCH*NH*SEQ*HD];     // [B,H,T,D]
__device__ __half g_v[BATCH*NH*SEQ*HD];     // [B,H,T,D]  (trans done by ldmatrix)
__device__ __half g_attn[BT*DIM];           // [B*T, C]
__device__ __half g_xh[BT*DIM];             // fp16(x)
__device__ __half g_wqkvh[QKVN*DIM];        // fp16(W_qkv^T)  [N][K]
__device__ __half g_wprojh[DIM*DIM];        // fp16(W_proj^T) [N][K]

// ---------------------------------------------------------------------------
__device__ __forceinline__ uint32_t smem_u32(const void* p) {
    uint32_t a;
    asm("{ .reg .u64 t; cvta.to.shared.u64 t, %1; cvt.u32.u64 %0, t; }" : "=r"(a) : "l"(p));
    return a;
}
__device__ __forceinline__ uint32_t pack_h2(float lo, float hi) {
    __half2 h = __floats2half2_rn(lo, hi);
    return *reinterpret_cast<uint32_t*>(&h);
}
#define CP16(dst, src) \
    asm volatile("cp.async.cg.shared.global [%0], [%1], 16;" :: "r"(dst), "l"(src) : "memory")
#define CPCOMMIT() asm volatile("cp.async.commit_group;" ::: "memory")
#define CPWAIT(n)  asm volatile("cp.async.wait_group %0;" :: "n"(n) : "memory")

// m16n8k16 fp16 mma, fp32 accum
__device__ __forceinline__ void mma16(float* c, const uint32_t* a, uint32_t b0, uint32_t b1) {
    asm volatile(
        "mma.sync.aligned.m16n8k16.row.col.f32.f16.f16.f32 "
        "{%0,%1,%2,%3},{%4,%5,%6,%7},{%8,%9},{%0,%1,%2,%3};\n"
        : "+f"(c[0]), "+f"(c[1]), "+f"(c[2]), "+f"(c[3])
        : "r"(a[0]), "r"(a[1]), "r"(a[2]), "r"(a[3]), "r"(b0), "r"(b1));
}

// ldmatrix x4: four 8x8 b16 matrices; lane l supplies row address
__device__ __forceinline__ void ldsm4(uint32_t* r, uint32_t addr) {
    asm volatile("ldmatrix.sync.aligned.m8n8.x4.shared.b16 {%0,%1,%2,%3}, [%4];"
                 : "=r"(r[0]), "=r"(r[1]), "=r"(r[2]), "=r"(r[3]) : "r"(addr));
}
// transposed variant: each 8x8 matrix individually transposed
__device__ __forceinline__ void ldsm4t(uint32_t* r, uint32_t addr) {
    asm volatile("ldmatrix.sync.aligned.m8n8.x4.trans.shared.b16 {%0,%1,%2,%3}, [%4];"
                 : "=r"(r[0]), "=r"(r[1]), "=r"(r[2]), "=r"(r[3]) : "r"(addr));
}

// ---------------------------------------------------------------------------
// Fused pre-convert: one launch.
// blocks [0, 2048): x fp32 -> fp16 elementwise (8 elems/thread)
// blocks [2048, 2048+4096): weight transpose [K][N] fp32 -> [N][K] fp16
// ---------------------------------------------------------------------------
#define CVT_XBLK 2048
#define CVT_WBLK 4096

__global__ void cvt_fused_kernel(const float* __restrict__ x, __half* __restrict__ xh,
                                 const float* __restrict__ w1, __half* __restrict__ d1,
                                 const float* __restrict__ w2, __half* __restrict__ d2) {
    __shared__ float tile[32][33];
    const int bid = blockIdx.x;
    const int tid = threadIdx.x;
    if (bid < CVT_XBLK) {
        int i = (bid * 256 + tid) * 8;
        float4 v0 = *(const float4*)(x + i);
        float4 v1 = *(const float4*)(x + i + 4);
        uint4 u = { pack_h2(v0.x, v0.y), pack_h2(v0.z, v0.w),
                    pack_h2(v1.x, v1.y), pack_h2(v1.z, v1.w) };
        *(uint4*)(xh + i) = u;
        return;
    }
    const int idx = bid - CVT_XBLK;
    const int bx  = idx & 127;
    const int k0  = (idx >> 7) * 32;
    const float* src;
    __half* dst;
    int N, n0;
    if (bx < QKVN / 32) { src = w1; dst = d1; N = QKVN; n0 = bx * 32; }
    else                { src = w2; dst = d2; N = DIM;  n0 = (bx - QKVN / 32) * 32; }
    const int tx = tid & 31, ty = tid >> 5;
    for (int i = ty; i < 32; i += 8)
        tile[i][tx] = src[(size_t)(k0 + i) * N + n0 + tx];
    __syncthreads();
    for (int i = ty; i < 32; i += 8)
        dst[(size_t)(n0 + i) * DIM + k0 + tx] = __float2half_rn(tile[tx][i]);
}

// ---------------------------------------------------------------------------
// fp16 GEMM: tile 128x128, BK=64, 3 stages cp.async (CPWAIT(1)), 256 threads,
// 2 CTAs/SM, warp tile 32x64, ldmatrix at 144 B stride. (frozen — plateau)
// MODE 0: QKV scatter (q, k, v all [B,H,T,D], packed 32-bit stores).
// MODE 1: C = acc + bias.
// ---------------------------------------------------------------------------
#define GA_ST 18432
#define GSTAGE (2 * GA_ST)             // A+B per stage: 36864
#define GSMEM (3 * GSTAGE)             // 110592 B -> 2 CTAs/SM

__device__ __forceinline__ void g_issue64(const __half* A, const __half* Bt,
                                          int m0, int n0, int t, int tid, uint32_t sb) {
    const uint32_t abase = sb + (t % 3) * GSTAGE;
    const uint32_t bbase = abase + GA_ST;
#pragma unroll
    for (int i = 0; i < 4; i++) {
        const int id = tid + i * 256;
        const int r = id >> 3, c = id & 7;
        CP16(abase + r * 144 + c * 16, A  + (size_t)(m0 + r) * 1024 + t * 64 + c * 8);
        CP16(bbase + r * 144 + c * 16, Bt + (size_t)(n0 + r) * 1024 + t * 64 + c * 8);
    }
    CPCOMMIT();
}

template<int MODE>
__global__ __launch_bounds__(256, 2)
void gemm_h(const __half* __restrict__ A, const __half* __restrict__ Bt,
            const float* __restrict__ bias, float* __restrict__ C, int N,
            __half* __restrict__ oq, __half* __restrict__ ok, __half* __restrict__ ov)
{
    extern __shared__ uint32_t sw[];
    const uint32_t sb = smem_u32(sw);

    const int tid  = threadIdx.x;
    const int lane = tid & 31;
    const int wid  = tid >> 5;
    const int g    = lane >> 2;
    const int tg   = lane & 3;
    const int warp_m = (wid & 3) * 32;
    const int warp_n = (wid >> 2) * 64;
    const int m0 = blockIdx.y * 128;
    const int n0 = blockIdx.x * 128;

    const int lrow = (lane & 7) + ((lane >> 3) & 1) * 8;
    const int lcol = lane >> 4;
    const uint32_t aOff = (uint32_t)((warp_m + lrow) * 144 + lcol * 16);
    const uint32_t bOff = (uint32_t)((warp_n + lrow) * 144 + lcol * 16);

    float acc[2][8][4];
#pragma unroll
    for (int mt = 0; mt < 2; mt++)
#pragma unroll
        for (int nt = 0; nt < 8; nt++)
#pragma unroll
            for (int i = 0; i < 4; i++) acc[mt][nt][i] = 0.f;

    g_issue64(A, Bt, m0, n0, 0, tid, sb);
    g_issue64(A, Bt, m0, n0, 1, tid, sb);

    for (int t = 0; t < 16; ++t) {
        if (t < 15) { CPWAIT(1); } else { CPWAIT(0); }
        __syncthreads();
        if (t + 2 < 16) g_issue64(A, Bt, m0, n0, t + 2, tid, sb);

        const uint32_t aS = sb + (t % 3) * GSTAGE;
        const uint32_t bS = aS + GA_ST;

#pragma unroll
        for (int kt = 0; kt < 4; ++kt) {
            uint32_t afr[2][4];
            ldsm4(afr[0], aS + aOff + kt * 32);
            ldsm4(afr[1], aS + aOff + 2304 + kt * 32);
            uint32_t bfr[4][4];
#pragma unroll
            for (int ntp = 0; ntp < 4; ntp++)
                ldsm4(bfr[ntp], bS + bOff + ntp * 2304 + kt * 32);
#pragma unroll
            for (int mt = 0; mt < 2; mt++)
#pragma unroll
                for (int ntp = 0; ntp < 4; ntp++) {
                    mma16(acc[mt][2*ntp],   afr[mt], bfr[ntp][0], bfr[ntp][2]);
                    mma16(acc[mt][2*ntp+1], afr[mt], bfr[ntp][1], bfr[ntp][3]);
                }
        }
    }

    // epilogue
    const int rowB = m0 + warp_m;
    const int colB = n0 + warp_n;
#pragma unroll
    for (int mt = 0; mt < 2; mt++) {
#pragma unroll
        for (int nt = 0; nt < 8; nt++) {
            const int r = rowB + mt * 16 + g;
            const int c = colB + nt * 8 + 2 * tg;
            const float bv0 = bias[c], bv1 = bias[c + 1];
            const float v00 = acc[mt][nt][0] + bv0;
            const float v01 = acc[mt][nt][1] + bv1;
            const float v10 = acc[mt][nt][2] + bv0;
            const float v11 = acc[mt][nt][3] + bv1;
            if (MODE == 0) {
                const int sel = c >> 10;
                const int cc  = c & 1023;
                const int h   = cc >> 6;
                const int d   = cc & 63;
                const int b0_ = r >> 11,        t0_ = r & 2047;
                const int b1_ = (r + 8) >> 11,  t1_ = (r + 8) & 2047;
                __half* dst = (sel == 0) ? oq : (sel == 1) ? ok : ov;
                const size_t i0 = (((size_t)(b0_ * NH + h) * SEQ) + t0_) * HD + d;
                const size_t i1 = (((size_t)(b1_ * NH + h) * SEQ) + t1_) * HD + d;
                *(uint32_t*)&dst[i0] = pack_h2(v00, v01);
                *(uint32_t*)&dst[i1] = pack_h2(v10, v11);
            } else {
                *(float2*)&C[(size_t)r * N + c]       = make_float2(v00, v01);
                *(float2*)&C[(size_t)(r + 8) * N + c] = make_float2(v10, v11);
            }
        }
    }
}

// ---------------------------------------------------------------------------
// Flash attention, fp16 m16n8k16, Br=128 x Bc=64, 256 threads, 2 CTAs/SM.
// FA2 register-P; Q pre-scaled 0.125; 3-buffer KV ring (one sync/tile);
// exp2 softmax; tensor-core row sums; last-tile skip; V stored [t][d] like K
// and loaded via ldmatrix.trans (fragments as-if [d][t]).
// ---------------------------------------------------------------------------
#define KVBUF 9216                     // 64 rows * 144 B
#define AQ_BYTES 18432                 // Q region: 128 * 144
#define ASMEM (AQ_BYTES + 6 * KVBUF)   // 73728 B -> 2 CTAs/SM

__device__ __forceinline__ void issue_kv(const __half* k, const __half* v,
                                         int bh, int kb, int buf, int tid,
                                         uint32_t kbase, uint32_t vbase) {
    const __half* ksrc = k + ((size_t)bh * SEQ + (size_t)kb * 64) * HD;
    const __half* vsrc = v + ((size_t)bh * SEQ + (size_t)kb * 64) * HD;
    const uint32_t kb_ = kbase + buf * KVBUF;
    const uint32_t vb_ = vbase + buf * KVBUF;
#pragma unroll
    for (int i = 0; i < 2; i++) {
        const int id = tid + i * 256;
        const int r = id >> 3, c = id & 7;
        CP16(kb_ + r * 144 + c * 16, ksrc + (size_t)r * HD + c * 8);
        CP16(vb_ + r * 144 + c * 16, vsrc + (size_t)r * HD + c * 8);
    }
    CPCOMMIT();
}

__global__ __launch_bounds__(256, 2)
void attn_h(const __half* __restrict__ q, const __half* __restrict__ k,
            const __half* __restrict__ v, __half* __restrict__ out)
{
    extern __shared__ uint32_t sw[];
    const uint32_t sb    = smem_u32(sw);
    const uint32_t kbase = sb + AQ_BYTES;
    const uint32_t vbase = kbase + 3 * KVBUF;

    const int tid  = threadIdx.x;
    const int lane = tid & 31;
    const int wid  = tid >> 5;
    const int g    = lane >> 2;
    const int tg   = lane & 3;
    const int wbase = wid * 16;

    const int lrow = (lane & 7) + ((lane >> 3) & 1) * 8;
    const int lcol = lane >> 4;
    const uint32_t qpOff = (uint32_t)((wbase + lrow) * 144 + lcol * 16);
    const uint32_t kvOff = (uint32_t)(lrow * 144 + lcol * 16);

    const int bh = blockIdx.y;
    const int qb = (gridDim.x - 1) - blockIdx.x;   // big tiles first
    const int b_ = bh >> 4;
    const int h  = bh & 15;
    const int diag0 = 2 * qb;                      // first diagonal tile idx
    const int nkv = diag0 + 2;
    const uint32_t ONES2 = 0x3C003C00u;            // (1.0h, 1.0h)

    // prologue: G0 = Q + KV0 (buf 0), G1 = KV1 (buf 1)
    {
        const __half* qsrc = q + ((size_t)bh * SEQ + (size_t)qb * 128) * HD;
#pragma unroll
        for (int i = 0; i < 4; i++) {
            const int id = tid + i * 256;
            const int r = id >> 3, c = id & 7;
            CP16(sb + r * 144 + c * 16, qsrc + (size_t)r * HD + c * 8);
        }
        const __half* ksrc = k + (size_t)bh * SEQ * HD;
        const __half* vsrc = v + (size_t)bh * SEQ * HD;
#pragma unroll
        for (int i = 0; i < 2; i++) {
            const int id = tid + i * 256;
            const int r = id >> 3, c = id & 7;
            CP16(kbase + r * 144 + c * 16, ksrc + (size_t)r * HD + c * 8);
            CP16(vbase + r * 144 + c * 16, vsrc + (size_t)r * HD + c * 8);
        }
        CPCOMMIT();
        issue_kv(k, v, bh, 1, 1, tid, kbase, vbase);
    }
    CPWAIT(1);
    __syncthreads();

    // Q fragments in registers, pre-scaled by 1/sqrt(64)=0.125 (exact in fp16)
    uint32_t qf[4][4];
    {
        const __half2 sc = __half2half2(__float2half_rn(0.125f));
#pragma unroll
        for (int kt = 0; kt < 4; kt++) {
            ldsm4(qf[kt], sb + qpOff + kt * 32);
#pragma unroll
            for (int i = 0; i < 4; i++) {
                __half2 vv = *reinterpret_cast<__half2*>(&qf[kt][i]);
                vv = __hmul2(vv, sc);
                qf[kt][i] = *reinterpret_cast<uint32_t*>(&vv);
            }
        }
    }

    const float L2E = 1.4426950408889634f;
    float m0 = -INFINITY, m1 = -INFINITY;     // raw-domain running max
    float m0_2 = -INFINITY, m1_2 = -INFINITY; // log2-domain (m * L2E)
    float l0 = 0.f, l1 = 0.f;
    float O[8][4];
#pragma unroll
    for (int nt = 0; nt < 8; nt++)
#pragma unroll
        for (int i = 0; i < 4; i++) O[nt][i] = 0.f;

    for (int kb = 0; kb < nkv; ++kb) {
        if (kb > 0) {
            if (kb + 1 < nkv) { CPWAIT(1); } else { CPWAIT(0); }
            __syncthreads();   // also fences reads of tile kb-1's buffers
        }
        if (kb + 2 < nkv) issue_kv(k, v, bh, kb + 2, (kb + 2) % 3, tid, kbase, vbase);

        // Last diagonal tile: rows 0-63 fully masked (P==0, m/l/O unchanged).
        if (kb == diag0 + 1 && wid < 4) continue;

        const uint32_t kB = kbase + (kb % 3) * KVBUF;
        const uint32_t vB = vbase + (kb % 3) * KVBUF;

        // S = (Q/8) @ K^T
        float s_[8][4];
#pragma unroll
        for (int nt = 0; nt < 8; nt++)
#pragma unroll
            for (int i = 0; i < 4; i++) s_[nt][i] = 0.f;
#pragma unroll
        for (int kt = 0; kt < 4; kt++) {
            uint32_t bfr[4][4];
#pragma unroll
            for (int ntp = 0; ntp < 4; ntp++)
                ldsm4(bfr[ntp], kB + kvOff + ntp * 2304 + kt * 32);
#pragma unroll
            for (int ntp = 0; ntp < 4; ntp++) {
                mma16(s_[2*ntp],   qf[kt], bfr[ntp][0], bfr[ntp][2]);
                mma16(s_[2*ntp+1], qf[kt], bfr[ntp][1], bfr[ntp][3]);
            }
        }

        // causal mask — only where it can trigger:
        //   kb==diag0   -> only warps 0-3 cross the diagonal
        //   kb==diag0+1 -> only warps 4-7 (0-3 already skipped)
        if (kb >= diag0 && ((wid < 4) == (kb == diag0))) {
            const int rg0 = qb * 128 + wbase + g;
#pragma unroll
            for (int nt = 0; nt < 8; nt++) {
                const int cg = kb * 64 + nt * 8 + 2 * tg;
                if (cg > rg0)         s_[nt][0] = -INFINITY;
                if (cg + 1 > rg0)     s_[nt][1] = -INFINITY;
                if (cg > rg0 + 8)     s_[nt][2] = -INFINITY;
                if (cg + 1 > rg0 + 8) s_[nt][3] = -INFINITY;
            }
        }

        // online softmax (log2 domain); row max via quad shuffle
        float mx0 = -INFINITY, mx1 = -INFINITY;
#pragma unroll
        for (int nt = 0; nt < 8; nt++) {
            mx0 = fmaxf(mx0, fmaxf(s_[nt][0], s_[nt][1]));
            mx1 = fmaxf(mx1, fmaxf(s_[nt][2], s_[nt][3]));
        }
#pragma unroll
        for (int off = 1; off < 4; off <<= 1) {
            mx0 = fmaxf(mx0, __shfl_xor_sync(0xffffffffu, mx0, off));
            mx1 = fmaxf(mx1, __shfl_xor_sync(0xffffffffu, mx1, off));
        }
        const float mn0 = fmaxf(m0, mx0);
        const float mn1 = fmaxf(m1, mx1);
        const float mn0_2 = mn0 * L2E;
        const float mn1_2 = mn1 * L2E;
        const float al0 = exp2f(m0_2 - mn0_2);
        const float al1 = exp2f(m1_2 - mn1_2);
        m0 = mn0; m1 = mn1; m0_2 = mn0_2; m1_2 = mn1_2;
        const float nm0 = -mn0_2, nm1 = -mn1_2;

        // exponentiate (row sum comes from the MMA below)
#pragma unroll
        for (int nt = 0; nt < 8; nt++) {
            s_[nt][0] = exp2f(fmaf(s_[nt][0], L2E, nm0));
            s_[nt][1] = exp2f(fmaf(s_[nt][1], L2E, nm0));
            s_[nt][2] = exp2f(fmaf(s_[nt][2], L2E, nm1));
            s_[nt][3] = exp2f(fmaf(s_[nt][3], L2E, nm1));
        }
#pragma unroll
        for (int nt = 0; nt < 8; nt++) {
            O[nt][0] *= al0; O[nt][1] *= al0;
            O[nt][2] *= al1; O[nt][3] *= al1;
        }

        // P stays in registers; O += P @ V and lsum += P @ ones (tensor core)
        // V fragments via ldmatrix.trans on [t][d] tile:
        //   m0=(d0-7,t0-7) m1=(d0-7,t8-15) m2=(d8-15,t0-7) m3=(d8-15,t8-15)
        float lsum[4] = {0.f, 0.f, 0.f, 0.f};
#pragma unroll
        for (int kt = 0; kt < 4; kt++) {
            uint32_t pa[4];
            pa[0] = pack_h2(s_[2*kt][0],   s_[2*kt][1]);
            pa[1] = pack_h2(s_[2*kt][2],   s_[2*kt][3]);
            pa[2] = pack_h2(s_[2*kt+1][0], s_[2*kt+1][1]);
            pa[3] = pack_h2(s_[2*kt+1][2], s_[2*kt+1][3]);
            uint32_t bfr[4][4];
#pragma unroll
            for (int ntp = 0; ntp < 4; ntp++)
                ldsm4t(bfr[ntp], vB + kvOff + kt * 2304 + ntp * 32);
#pragma unroll
            for (int ntp = 0; ntp < 4; ntp++) {
                mma16(O[2*ntp],   pa, bfr[ntp][0], bfr[ntp][1]);
                mma16(O[2*ntp+1], pa, bfr[ntp][2], bfr[ntp][3]);
            }
            mma16(lsum, pa, ONES2, ONES2);   // row sums (quad-wide via k-reduce)
        }
        l0 = l0 * al0 + lsum[0];
        l1 = l1 * al1 + lsum[2];
        // no bottom sync: 3-buffer ring defers the reuse guard to next top sync
    }

    // normalize, write fp16 to g_attn [B*T, C]
    const float inv0 = 1.f / l0;
    const float inv1 = 1.f / l1;
    const int t0 = qb * 128 + wbase + g;
#pragma unroll
    for (int nt = 0; nt < 8; nt++) {
        const int c = h * HD + nt * 8 + 2 * tg;
        *(uint32_t*)&out[((size_t)(b_ * SEQ + t0)) * DIM + c] =
            pack_h2(O[nt][0] * inv0, O[nt][1] * inv0);
        *(uint32_t*)&out[((size_t)(b_ * SEQ + t0 + 8)) * DIM + c] =
            pack_h2(O[nt][2] * inv1, O[nt][3] * inv1);
    }
}

// ---------------------------------------------------------------------------
extern "C" void kernel_launch(void* const* d_in, const int* in_sizes, int n_in,
                              void* d_out, int out_size)
{
    const float* x     = (const float*)d_in[0];
    const float* Wqkv  = (const float*)d_in[1];
    const float* bqkv  = (const float*)d_in[2];
    const float* Wproj = (const float*)d_in[3];
    const float* bproj = (const float*)d_in[4];
    float* out = (float*)d_out;

    __half *gq, *gk, *gv, *gattn, *gxh, *gwqkvh, *gwprojh;
    cudaGetSymbolAddress((void**)&gq, g_q);
    cudaGetSymbolAddress((void**)&gk, g_k);
    cudaGetSymbolAddress((void**)&gv, g_v);
    cudaGetSymbolAddress((void**)&gattn, g_attn);
    cudaGetSymbolAddress((void**)&gxh, g_xh);
    cudaGetSymbolAddress((void**)&gwqkvh, g_wqkvh);
    cudaGetSymbolAddress((void**)&gwprojh, g_wprojh);

    cudaFuncSetAttribute(gemm_h<0>, cudaFuncAttributeMaxDynamicSharedMemorySize, GSMEM);
    cudaFuncSetAttribute(gemm_h<1>, cudaFuncAttributeMaxDynamicSharedMemorySize, GSMEM);
    cudaFuncSetAttribute(attn_h,   cudaFuncAttributeMaxDynamicSharedMemorySize, ASMEM);

    // 0) fused fp16 pre-convert (x + both weight transposes, one launch)
    cvt_fused_kernel<<<CVT_XBLK + CVT_WBLK, 256>>>(x, gxh, Wqkv, gwqkvh, Wproj, gwprojh);

    // 1) QKV projection + head scatter (all of q,k,v in [B,H,T,D])
    {
        dim3 grid(QKVN / 128, BT / 128);   // (24, 32)
        gemm_h<0><<<grid, 256, GSMEM>>>(gxh, gwqkvh, bqkv, nullptr,
                                        QKVN, gq, gk, gv);
    }
    // 2) Causal flash attention (V transposed in-register via ldmatrix.trans)
    {
        dim3 grid(SEQ / 128, BATCH * NH);  // (16, 32)
        attn_h<<<grid, 256, ASMEM>>>(gq, gk, gv, gattn);
    }
    // 3) Output projection
    {
        dim3 grid(DIM / 128, BT / 128);    // (8, 32)
        gemm_h<1><<<grid, 256, GSMEM>>>(gattn, gwprojh, bproj, out,
                                        DIM, nullptr, nullptr, nullptr);
    }
    (void)in_sizes; (void)n_in; (void)out_size;
}